// round 2
// baseline (speedup 1.0000x reference)
#include <cuda_runtime.h>
#include <math.h>

// Problem constants
#define NN   50000
#define EE   1600000
#define INF  64
#define HIDF 128
#define LATF 32
#define HARM 8
#define NL   3
#define NG   64

// ---------------- scratch (__device__ globals; no runtime allocation) ----------------
__device__ float g_h [NN * HIDF];          // current node features
__device__ float g_hk[NN * HIDF];          // kan(h) before aggregation
__device__ int   g_deg [NN];               // degree incl. self loop
__device__ float g_dinv[NN];               // deg^-0.5
__device__ int   g_off [NN + 1];           // CSR offsets (edges only, by col)
__device__ int   g_cur [NN];               // fill cursors
__device__ int   g_rows[EE];               // CSR: source row per edge
__device__ float g_nrm [EE];               // CSR: dinv[row]*dinv[col] per edge
__device__ float g_wte [1024 * 128];       // W_embed transposed  [K=1024][128]
__device__ float g_wtm [3 * 2048 * 128];   // W_mp transposed     [l][K=2048][128]
__device__ float g_wtr [2048 * 32];        // W_read transposed   [K=2048][32]
__device__ float g_pool[NG * HIDF];        // pooled graph features

// packed f32x2 helpers (sm_103a FFMA2 path — only reachable via PTX fma.rn.f32x2)
#define PACKDUP(dst, s) asm("mov.b64 %0, {%1, %1};" : "=l"(dst) : "f"(s))
#define FMA2(c, a, b)   asm("fma.rn.f32x2 %0, %1, %2, %0;" : "+l"(c) : "l"(a), "l"(b))

// ---------------- weight repack: W[2][OUT][IN][8] -> Wt[k][o], k = i*16 + t*8 + h ----
__device__ __forceinline__ void transpose_body(const float* __restrict__ W,
                                               float* __restrict__ Wt,
                                               int INDIM, int OUT)
{
    int idx = blockIdx.x * blockDim.x + threadIdx.x;
    int total = INDIM * 16 * OUT;
    if (idx >= total) return;
    int o = idx % OUT;
    int k = idx / OUT;
    int i = k >> 4;
    int t = (k >> 3) & 1;
    int h = k & 7;
    Wt[idx] = W[(((size_t)t * OUT + o) * INDIM + i) * 8 + h];
}

__global__ void transpose_embed(const float* __restrict__ W) { transpose_body(W, g_wte, 64, 128); }
__global__ void transpose_mp(const float* __restrict__ W, int layer)
{
    transpose_body(W + (size_t)layer * 2 * 128 * 128 * 8, g_wtm + (size_t)layer * 2048 * 128, 128, 128);
}
__global__ void transpose_read(const float* __restrict__ W) { transpose_body(W, g_wtr, 128, 32); }

// ---------------- degree / dinv ----------------
__global__ void deg_init_kernel()
{
    int i = blockIdx.x * blockDim.x + threadIdx.x;
    if (i < NN) g_deg[i] = 1;   // self loop
}
__global__ void deg_count_kernel(const int* __restrict__ ei)
{
    int e = blockIdx.x * blockDim.x + threadIdx.x;
    if (e < EE) atomicAdd(&g_deg[ei[EE + e]], 1);
}
__global__ void dinv_kernel()
{
    int i = blockIdx.x * blockDim.x + threadIdx.x;
    if (i < NN) g_dinv[i] = rsqrtf((float)g_deg[i]);
}

// ---------------- CSR build: exclusive scan of (deg-1), then fill ----------------
__global__ void scan_kernel()
{
    __shared__ int part[1024];
    int t = threadIdx.x;
    const int seg = (NN + 1023) / 1024;
    int base = t * seg;
    int s = 0;
    for (int j = 0; j < seg; ++j) {
        int i = base + j;
        if (i < NN) s += g_deg[i] - 1;
    }
    part[t] = s;
    __syncthreads();
    for (int d = 1; d < 1024; d <<= 1) {
        int v = (t >= d) ? part[t - d] : 0;
        __syncthreads();
        part[t] += v;
        __syncthreads();
    }
    int run = part[t] - s;
    for (int j = 0; j < seg; ++j) {
        int i = base + j;
        if (i < NN) {
            g_off[i] = run;
            g_cur[i] = run;
            run += g_deg[i] - 1;
        }
    }
    if (t == 1023) g_off[NN] = part[1023];
}

__global__ void fill_kernel(const int* __restrict__ ei)
{
    int e = blockIdx.x * blockDim.x + threadIdx.x;
    if (e >= EE) return;
    int r = ei[e];
    int c = ei[EE + e];
    int pos = atomicAdd(&g_cur[c], 1);
    g_rows[pos] = r;
    g_nrm[pos]  = g_dinv[r] * g_dinv[c];
}

// ---------------- KAN GEMM: Y[rows,128] = phi(X) @ Wt  (FFMA2 packed f32x2) --------
// Tile: 64 rows x 128 cols, 256 threads.
// Micro-tile: 4 rows x 8 cols per thread, cols in two groups {tx*4..+3, 64+tx*4..+3}
// (contiguous float4 groups -> conflict-free LDS.128 phases).
// K-chunk = 32 (= 2 input dims x 16 trig features), trig built on the fly in smem.
template <int INDIM>
__device__ __forceinline__ void kan_body(const float* __restrict__ X,
                                         const float* __restrict__ Wt,
                                         float* __restrict__ Y, int nrows)
{
    __shared__ float phiS[32 * 64];   // [k_local][row]   8 KB
    __shared__ float wS  [32 * 128];  // [k_local][o]    16 KB

    const int tid = threadIdx.x;
    const int tx  = tid & 15;           // col-group index
    const int ty  = tid >> 4;           // row-quad index (0..15)
    const int rowBase = blockIdx.x * 64;

    unsigned long long acc[4][4];       // [row][colpair]: pairs (2 cols) packed f32x2
#pragma unroll
    for (int i = 0; i < 4; ++i)
#pragma unroll
        for (int j = 0; j < 4; ++j) acc[i][j] = 0ull;

    const int NCH = INDIM / 2;
    for (int ch = 0; ch < NCH; ++ch) {
        __syncthreads();
        if (tid < 128) {
            // thread t: row = t>>1, dim = t&1 -> 16 phi values via harmonic recurrence
            int row = tid >> 1;
            int d   = tid & 1;
            int r   = rowBase + row;
            float x = 0.f;
            if (r < nrows) x = X[(size_t)r * INDIM + ch * 2 + d];
            float s1, c1;
            __sincosf(x, &s1, &c1);
            float ck = c1, sk = s1;
            int kb = d * 16;
#pragma unroll
            for (int hh = 0; hh < 8; ++hh) {
                phiS[(kb + hh) * 64 + row]     = ck;   // cos(k x), k = hh+1
                phiS[(kb + 8 + hh) * 64 + row] = sk;   // sin(k x)
                float cn = ck * c1 - sk * s1;
                sk = sk * c1 + ck * s1;
                ck = cn;
            }
        } else {
            // other 128 threads stream the W chunk (coalesced, pre-transposed)
            int t2 = tid - 128;
            const float4* src = (const float4*)(Wt + (size_t)ch * 32 * 128);
            float4* dst = (float4*)wS;
#pragma unroll
            for (int j = 0; j < 8; ++j) dst[t2 + j * 128] = src[t2 + j * 128];
        }
        __syncthreads();

#pragma unroll 4
        for (int k = 0; k < 32; ++k) {
            float4 av = *(const float4*)(phiS + k * 64 + ty * 4);
            ulonglong2 b0 = *(const ulonglong2*)(wS + k * 128 + tx * 4);        // cols tx*4..+3
            ulonglong2 b1 = *(const ulonglong2*)(wS + k * 128 + 64 + tx * 4);   // cols 64+tx*4..+3
            unsigned long long a2[4];
            PACKDUP(a2[0], av.x);
            PACKDUP(a2[1], av.y);
            PACKDUP(a2[2], av.z);
            PACKDUP(a2[3], av.w);
#pragma unroll
            for (int i = 0; i < 4; ++i) {
                FMA2(acc[i][0], a2[i], b0.x);
                FMA2(acc[i][1], a2[i], b0.y);
                FMA2(acc[i][2], a2[i], b1.x);
                FMA2(acc[i][3], a2[i], b1.y);
            }
        }
    }

#pragma unroll
    for (int i = 0; i < 4; ++i) {
        int r = rowBase + ty * 4 + i;
        if (r < nrows) {
            ulonglong2 o0; o0.x = acc[i][0]; o0.y = acc[i][1];
            ulonglong2 o1; o1.x = acc[i][2]; o1.y = acc[i][3];
            *(ulonglong2*)(Y + (size_t)r * 128 + tx * 4)      = o0;
            *(ulonglong2*)(Y + (size_t)r * 128 + 64 + tx * 4) = o1;
        }
    }
}

__global__ void __launch_bounds__(256, 2) kan_embed_kernel(const float* __restrict__ X)
{
    kan_body<64>(X, g_wte, g_h, NN);
}
__global__ void __launch_bounds__(256, 2) kan_mp_kernel(int layer)
{
    kan_body<128>(g_h, g_wtm + (size_t)layer * 2048 * 128, g_hk, NN);
}

// ---------------- aggregation: h[c] = dinv[c]^2 * hk[c] + sum_{e: col=c} nrm_e * hk[row_e] ----
// one warp per destination node, lane = float4 slot of the 128-wide feature row
__global__ void agg_kernel()
{
    int w    = (blockIdx.x * blockDim.x + threadIdx.x) >> 5;
    int lane = threadIdx.x & 31;
    if (w >= NN) return;

    float di = g_dinv[w];
    const float4* hk4 = (const float4*)g_hk;
    float4 v = hk4[(size_t)w * 32 + lane];
    float dd = di * di;
    float4 acc = make_float4(dd * v.x, dd * v.y, dd * v.z, dd * v.w);

    int s = g_off[w], e = g_off[w + 1];
    for (int idx = s; idx < e; ++idx) {
        int   r  = g_rows[idx];
        float nm = g_nrm[idx];
        float4 u = hk4[(size_t)r * 32 + lane];
        acc.x = fmaf(nm, u.x, acc.x);
        acc.y = fmaf(nm, u.y, acc.y);
        acc.z = fmaf(nm, u.z, acc.z);
        acc.w = fmaf(nm, u.w, acc.w);
    }
    ((float4*)g_h)[(size_t)w * 32 + lane] = acc;
}

// ---------------- mean pool per graph (batch ids are sorted) ----------------
__global__ void pool_kernel(const int* __restrict__ batch)
{
    int g = blockIdx.x;     // 64 graphs
    int f = threadIdx.x;    // 128 features

    int lo = 0, hi = NN;
    while (lo < hi) { int m = (lo + hi) >> 1; if (batch[m] < g) lo = m + 1; else hi = m; }
    int st = lo;
    lo = 0; hi = NN;
    while (lo < hi) { int m = (lo + hi) >> 1; if (batch[m] < g + 1) lo = m + 1; else hi = m; }
    int en = lo;

    float acc = 0.f;
    for (int n = st; n < en; ++n) acc += g_h[(size_t)n * 128 + f];
    float cnt = (float)(en - st);
    g_pool[g * 128 + f] = acc / fmaxf(cnt, 1.0f);
}

// ---------------- final readout: out[g, 32] = kan(pool[g], W_read) ----------------
__global__ void read_kernel(float* __restrict__ out)
{
    __shared__ float phi[2048];
    __shared__ float part[32 * 8];
    int g   = blockIdx.x;
    int tid = threadIdx.x;

    if (tid < 128) {
        float x = g_pool[g * 128 + tid];
        float s1, c1;
        sincosf(x, &s1, &c1);
        float ck = c1, sk = s1;
#pragma unroll
        for (int hh = 0; hh < 8; ++hh) {
            phi[tid * 16 + hh]     = ck;
            phi[tid * 16 + 8 + hh] = sk;
            float cn = ck * c1 - sk * s1;
            sk = sk * c1 + ck * s1;
            ck = cn;
        }
    }
    __syncthreads();

    int o = tid >> 3, sg = tid & 7;
    float acc = 0.f;
    int k0 = sg * 256;
    for (int k = k0; k < k0 + 256; ++k)
        acc = fmaf(phi[k], g_wtr[k * 32 + o], acc);
    part[o * 8 + sg] = acc;
    __syncthreads();

    if (tid < 32) {
        float s = 0.f;
#pragma unroll
        for (int j = 0; j < 8; ++j) s += part[tid * 8 + j];
        out[g * 32 + tid] = s;
    }
}

// ---------------- launch ----------------
extern "C" void kernel_launch(void* const* d_in, const int* in_sizes, int n_in,
                              void* d_out, int out_size)
{
    const float* features = (const float*)d_in[0];
    const int*   ei       = (const int*)  d_in[1];
    const int*   batch    = (const int*)  d_in[2];
    const float* W_embed  = (const float*)d_in[3];
    const float* W_mp     = (const float*)d_in[4];
    const float* W_read   = (const float*)d_in[5];
    float* out = (float*)d_out;

    // 1. repack weights to K-major
    transpose_embed<<<(1024 * 128 + 255) / 256, 256>>>(W_embed);
    for (int l = 0; l < NL; ++l)
        transpose_mp<<<(2048 * 128 + 255) / 256, 256>>>(W_mp, l);
    transpose_read<<<(2048 * 32 + 255) / 256, 256>>>(W_read);

    // 2. degrees + dinv
    deg_init_kernel <<<(NN + 255) / 256, 256>>>();
    deg_count_kernel<<<(EE + 255) / 256, 256>>>(ei);
    dinv_kernel     <<<(NN + 255) / 256, 256>>>();

    // 3. CSR build (by destination col)
    scan_kernel<<<1, 1024>>>();
    fill_kernel<<<(EE + 255) / 256, 256>>>(ei);

    // 4. embed
    const int GK = (NN + 63) / 64;   // 782 tiles of 64 rows
    kan_embed_kernel<<<GK, 256>>>(features);

    // 5. message-passing layers: kan -> gather-aggregate
    for (int l = 0; l < NL; ++l) {
        kan_mp_kernel<<<GK, 256>>>(l);
        agg_kernel<<<(NN * 32 + 255) / 256, 256>>>();
    }

    // 6. pool + readout
    pool_kernel<<<NG, 128>>>(batch);
    read_kernel<<<NG, 256>>>(out);
}

// round 3
// speedup vs baseline: 1.1327x; 1.1327x over previous
#include <cuda_runtime.h>
#include <math.h>

// Problem constants
#define NN   50000
#define EE   1600000
#define INF  64
#define HIDF 128
#define LATF 32
#define HARM 8
#define NL   3
#define NG   64

// ---------------- scratch (__device__ globals; no runtime allocation) ----------------
__device__ float g_h [NN * HIDF];          // current node features
__device__ float g_hk[NN * HIDF];          // kan(h) before aggregation
__device__ int   g_deg [NN];               // degree incl. self loop
__device__ float g_dinv[NN];               // deg^-0.5
__device__ int   g_off [NN + 1];           // CSR offsets (edges only, by col)
__device__ int   g_cur [NN];               // fill cursors
__device__ int   g_rows[EE];               // CSR: source row per edge
__device__ float g_nrm [EE];               // CSR: dinv[row]*dinv[col] per edge
__device__ float g_wte [1024 * 128];       // W_embed transposed  [K=1024][128]
__device__ float g_wtm [3 * 2048 * 128];   // W_mp transposed     [l][K=2048][128]
__device__ float g_wtr [2048 * 32];        // W_read transposed   [K=2048][32]
__device__ float g_pool[NG * HIDF];        // pooled graph features

// packed f32x2 helpers (sm_103a FFMA2 path — only reachable via PTX fma.rn.f32x2)
#define PACKDUP(dst, s) asm("mov.b64 %0, {%1, %1};" : "=l"(dst) : "f"(s))
#define FMA2(c, a, b)   asm("fma.rn.f32x2 %0, %1, %2, %0;" : "+l"(c) : "l"(a), "l"(b))

// ---------------- weight repack: W[2][OUT][IN][8] -> Wt[k][o], k = i*16 + t*8 + h ----
__device__ __forceinline__ void transpose_body(const float* __restrict__ W,
                                               float* __restrict__ Wt,
                                               int INDIM, int OUT)
{
    int idx = blockIdx.x * blockDim.x + threadIdx.x;
    int total = INDIM * 16 * OUT;
    if (idx >= total) return;
    int o = idx % OUT;
    int k = idx / OUT;
    int i = k >> 4;
    int t = (k >> 3) & 1;
    int h = k & 7;
    Wt[idx] = W[(((size_t)t * OUT + o) * INDIM + i) * 8 + h];
}

__global__ void transpose_embed(const float* __restrict__ W) { transpose_body(W, g_wte, 64, 128); }
__global__ void transpose_mp(const float* __restrict__ W, int layer)
{
    transpose_body(W + (size_t)layer * 2 * 128 * 128 * 8, g_wtm + (size_t)layer * 2048 * 128, 128, 128);
}
__global__ void transpose_read(const float* __restrict__ W) { transpose_body(W, g_wtr, 128, 32); }

// ---------------- degree / dinv ----------------
__global__ void deg_init_kernel()
{
    int i = blockIdx.x * blockDim.x + threadIdx.x;
    if (i < NN) g_deg[i] = 1;   // self loop
}
__global__ void deg_count_kernel(const int* __restrict__ ei)
{
    int e = blockIdx.x * blockDim.x + threadIdx.x;
    if (e < EE) atomicAdd(&g_deg[ei[EE + e]], 1);
}
__global__ void dinv_kernel()
{
    int i = blockIdx.x * blockDim.x + threadIdx.x;
    if (i < NN) g_dinv[i] = rsqrtf((float)g_deg[i]);
}

// ---------------- CSR build: exclusive scan of (deg-1), then fill ----------------
__global__ void scan_kernel()
{
    __shared__ int part[1024];
    int t = threadIdx.x;
    const int seg = (NN + 1023) / 1024;
    int base = t * seg;
    int s = 0;
    for (int j = 0; j < seg; ++j) {
        int i = base + j;
        if (i < NN) s += g_deg[i] - 1;
    }
    part[t] = s;
    __syncthreads();
    for (int d = 1; d < 1024; d <<= 1) {
        int v = (t >= d) ? part[t - d] : 0;
        __syncthreads();
        part[t] += v;
        __syncthreads();
    }
    int run = part[t] - s;
    for (int j = 0; j < seg; ++j) {
        int i = base + j;
        if (i < NN) {
            g_off[i] = run;
            g_cur[i] = run;
            run += g_deg[i] - 1;
        }
    }
    if (t == 1023) g_off[NN] = part[1023];
}

__global__ void fill_kernel(const int* __restrict__ ei)
{
    int e = blockIdx.x * blockDim.x + threadIdx.x;
    if (e >= EE) return;
    int r = ei[e];
    int c = ei[EE + e];
    int pos = atomicAdd(&g_cur[c], 1);
    g_rows[pos] = r;
    g_nrm[pos]  = g_dinv[r] * g_dinv[c];
}

// ---------------- KAN GEMM: Y[rows,128] = phi(X) @ Wt  (FFMA2, 8x8 micro-tile) ------
// Tile: 64 rows x 128 cols, 128 threads. Micro-tile: 8 rows x 8 cols per thread
// (8 col slots as 4 packed col-pairs). 32 FFMA2 per k per thread -> FMA-pipe bound
// with issue slack for the 16 dup-MOVs and 4 LDS.
// K-chunk = 32 (= 2 input dims x 16 trig features), trig built on the fly in smem.
template <int INDIM>
__device__ __forceinline__ void kan_body(const float* __restrict__ X,
                                         const float* __restrict__ Wt,
                                         float* __restrict__ Y, int nrows)
{
    __shared__ float phiS[32 * 64];   // [k_local][row]   8 KB
    __shared__ float wS  [32 * 128];  // [k_local][o]    16 KB

    const int tid = threadIdx.x;      // 128 threads
    const int tx  = tid & 15;         // col group (0..15)
    const int ty  = tid >> 4;         // row group (0..7)
    const int rowBase = blockIdx.x * 64;

    unsigned long long acc[8][4];     // [row][colpair] packed f32x2
#pragma unroll
    for (int i = 0; i < 8; ++i)
#pragma unroll
        for (int j = 0; j < 4; ++j) acc[i][j] = 0ull;

    const int NCH = INDIM / 2;
    for (int ch = 0; ch < NCH; ++ch) {
        __syncthreads();
        {
            // phi generation: thread t -> row = t>>1, dim = t&1 (64 rows x 2 dims)
            int row = tid >> 1;
            int d   = tid & 1;
            int r   = rowBase + row;
            float x = 0.f;
            if (r < nrows) x = X[(size_t)r * INDIM + ch * 2 + d];
            float s1, c1;
            __sincosf(x, &s1, &c1);
            float ck = c1, sk = s1;
            int kb = d * 16;
#pragma unroll
            for (int hh = 0; hh < 8; ++hh) {
                phiS[(kb + hh) * 64 + row]     = ck;   // cos(k x), k = hh+1
                phiS[(kb + 8 + hh) * 64 + row] = sk;   // sin(k x)
                float cn = ck * c1 - sk * s1;
                sk = sk * c1 + ck * s1;
                ck = cn;
            }
        }
        {
            // stream the W chunk (coalesced, pre-transposed): 1024 float4s / 128 thr
            const float4* src = (const float4*)(Wt + (size_t)ch * 32 * 128);
            float4* dst = (float4*)wS;
#pragma unroll
            for (int j = 0; j < 8; ++j) dst[tid + j * 128] = src[tid + j * 128];
        }
        __syncthreads();

#pragma unroll 4
        for (int k = 0; k < 32; ++k) {
            float4 a0 = *(const float4*)(phiS + k * 64 + ty * 8);
            float4 a1 = *(const float4*)(phiS + k * 64 + ty * 8 + 4);
            ulonglong2 b0 = *(const ulonglong2*)(wS + k * 128 + tx * 4);        // cols tx*4..+3
            ulonglong2 b1 = *(const ulonglong2*)(wS + k * 128 + 64 + tx * 4);   // cols 64+tx*4..+3
            unsigned long long a2[8];
            PACKDUP(a2[0], a0.x);
            PACKDUP(a2[1], a0.y);
            PACKDUP(a2[2], a0.z);
            PACKDUP(a2[3], a0.w);
            PACKDUP(a2[4], a1.x);
            PACKDUP(a2[5], a1.y);
            PACKDUP(a2[6], a1.z);
            PACKDUP(a2[7], a1.w);
#pragma unroll
            for (int i = 0; i < 8; ++i) {
                FMA2(acc[i][0], a2[i], b0.x);
                FMA2(acc[i][1], a2[i], b0.y);
                FMA2(acc[i][2], a2[i], b1.x);
                FMA2(acc[i][3], a2[i], b1.y);
            }
        }
    }

#pragma unroll
    for (int i = 0; i < 8; ++i) {
        int r = rowBase + ty * 8 + i;
        if (r < nrows) {
            ulonglong2 o0; o0.x = acc[i][0]; o0.y = acc[i][1];
            ulonglong2 o1; o1.x = acc[i][2]; o1.y = acc[i][3];
            *(ulonglong2*)(Y + (size_t)r * 128 + tx * 4)      = o0;
            *(ulonglong2*)(Y + (size_t)r * 128 + 64 + tx * 4) = o1;
        }
    }
}

__global__ void __launch_bounds__(128, 4) kan_embed_kernel(const float* __restrict__ X)
{
    kan_body<64>(X, g_wte, g_h, NN);
}
__global__ void __launch_bounds__(128, 4) kan_mp_kernel(int layer)
{
    kan_body<128>(g_h, g_wtm + (size_t)layer * 2048 * 128, g_hk, NN);
}

// ---------------- aggregation: h[c] = dinv[c]^2 * hk[c] + sum_{e: col=c} nrm_e * hk[row_e] ----
// one warp per destination node, lane = float4 slot of the 128-wide feature row
__global__ void agg_kernel()
{
    int w    = (blockIdx.x * blockDim.x + threadIdx.x) >> 5;
    int lane = threadIdx.x & 31;
    if (w >= NN) return;

    float di = g_dinv[w];
    const float4* hk4 = (const float4*)g_hk;
    float4 v = hk4[(size_t)w * 32 + lane];
    float dd = di * di;
    float4 acc = make_float4(dd * v.x, dd * v.y, dd * v.z, dd * v.w);

    int s = g_off[w], e = g_off[w + 1];
    for (int idx = s; idx < e; ++idx) {
        int   r  = g_rows[idx];
        float nm = g_nrm[idx];
        float4 u = hk4[(size_t)r * 32 + lane];
        acc.x = fmaf(nm, u.x, acc.x);
        acc.y = fmaf(nm, u.y, acc.y);
        acc.z = fmaf(nm, u.z, acc.z);
        acc.w = fmaf(nm, u.w, acc.w);
    }
    ((float4*)g_h)[(size_t)w * 32 + lane] = acc;
}

// ---------------- mean pool per graph (batch ids are sorted) ----------------
__global__ void pool_kernel(const int* __restrict__ batch)
{
    int g = blockIdx.x;     // 64 graphs
    int f = threadIdx.x;    // 128 features

    int lo = 0, hi = NN;
    while (lo < hi) { int m = (lo + hi) >> 1; if (batch[m] < g) lo = m + 1; else hi = m; }
    int st = lo;
    lo = 0; hi = NN;
    while (lo < hi) { int m = (lo + hi) >> 1; if (batch[m] < g + 1) lo = m + 1; else hi = m; }
    int en = lo;

    float acc = 0.f;
    for (int n = st; n < en; ++n) acc += g_h[(size_t)n * 128 + f];
    float cnt = (float)(en - st);
    g_pool[g * 128 + f] = acc / fmaxf(cnt, 1.0f);
}

// ---------------- final readout: out[g, 32] = kan(pool[g], W_read) ----------------
__global__ void read_kernel(float* __restrict__ out)
{
    __shared__ float phi[2048];
    __shared__ float part[32 * 8];
    int g   = blockIdx.x;
    int tid = threadIdx.x;

    if (tid < 128) {
        float x = g_pool[g * 128 + tid];
        float s1, c1;
        sincosf(x, &s1, &c1);
        float ck = c1, sk = s1;
#pragma unroll
        for (int hh = 0; hh < 8; ++hh) {
            phi[tid * 16 + hh]     = ck;
            phi[tid * 16 + 8 + hh] = sk;
            float cn = ck * c1 - sk * s1;
            sk = sk * c1 + ck * s1;
            ck = cn;
        }
    }
    __syncthreads();

    int o = tid >> 3, sg = tid & 7;
    float acc = 0.f;
    int k0 = sg * 256;
    for (int k = k0; k < k0 + 256; ++k)
        acc = fmaf(phi[k], g_wtr[k * 32 + o], acc);
    part[o * 8 + sg] = acc;
    __syncthreads();

    if (tid < 32) {
        float s = 0.f;
#pragma unroll
        for (int j = 0; j < 8; ++j) s += part[tid * 8 + j];
        out[g * 32 + tid] = s;
    }
}

// ---------------- launch ----------------
extern "C" void kernel_launch(void* const* d_in, const int* in_sizes, int n_in,
                              void* d_out, int out_size)
{
    const float* features = (const float*)d_in[0];
    const int*   ei       = (const int*)  d_in[1];
    const int*   batch    = (const int*)  d_in[2];
    const float* W_embed  = (const float*)d_in[3];
    const float* W_mp     = (const float*)d_in[4];
    const float* W_read   = (const float*)d_in[5];
    float* out = (float*)d_out;

    // 1. repack weights to K-major
    transpose_embed<<<(1024 * 128 + 255) / 256, 256>>>(W_embed);
    for (int l = 0; l < NL; ++l)
        transpose_mp<<<(2048 * 128 + 255) / 256, 256>>>(W_mp, l);
    transpose_read<<<(2048 * 32 + 255) / 256, 256>>>(W_read);

    // 2. degrees + dinv
    deg_init_kernel <<<(NN + 255) / 256, 256>>>();
    deg_count_kernel<<<(EE + 255) / 256, 256>>>(ei);
    dinv_kernel     <<<(NN + 255) / 256, 256>>>();

    // 3. CSR build (by destination col)
    scan_kernel<<<1, 1024>>>();
    fill_kernel<<<(EE + 255) / 256, 256>>>(ei);

    // 4. embed
    const int GK = (NN + 63) / 64;   // 782 tiles of 64 rows
    kan_embed_kernel<<<GK, 128>>>(features);

    // 5. message-passing layers: kan -> gather-aggregate
    for (int l = 0; l < NL; ++l) {
        kan_mp_kernel<<<GK, 128>>>(l);
        agg_kernel<<<(NN * 32 + 255) / 256, 256>>>();
    }

    // 6. pool + readout
    pool_kernel<<<NG, 128>>>(batch);
    read_kernel<<<NG, 256>>>(out);
}

// round 13
// speedup vs baseline: 2.1753x; 1.9204x over previous
#include <cuda_runtime.h>
#include <cuda_bf16.h>
#include <cstdint>
#include <stdint.h>
#include <math.h>

// Problem constants
#define NN   50000
#define EE   1600000
#define INF  64
#define HIDF 128
#define NG   64
#define NL   3

// ---------------- scratch (__device__ globals; no runtime allocation) ----------------
__device__ float g_h [NN * HIDF];
__device__ float g_hk[NN * HIDF];
__device__ int   g_deg [NN];
__device__ float g_dinv[NN];
__device__ int   g_off [NN + 1];
__device__ int   g_cur [NN];
__device__ int   g_rows[EE];
__device__ float g_nrm [EE];
__device__ __nv_bfloat16 g_wbh_e[128 * 1024];       // embed W hi, [o][k]
__device__ __nv_bfloat16 g_wbl_e[128 * 1024];       // embed W lo
__device__ __nv_bfloat16 g_wbh_m[3 * 128 * 2048];   // mp W hi, [l][o][k]
__device__ __nv_bfloat16 g_wbl_m[3 * 128 * 2048];   // mp W lo
__device__ float g_wtr [2048 * 32];                 // readout W fp32, [k][o]
__device__ float g_pool[NG * HIDF];

// ---------------- PTX helpers (base-target legal: ldmatrix + mma.sync) ----------------
__device__ __forceinline__ unsigned s2u(const void* p)
{
    unsigned a;
    asm("{ .reg .u64 t; cvta.to.shared.u64 t, %1; cvt.u32.u64 %0, t; }" : "=r"(a) : "l"(p));
    return a;
}

#define LDSM4(r0, r1, r2, r3, addr) \
    asm volatile("ldmatrix.sync.aligned.m8n8.x4.shared.b16 {%0,%1,%2,%3}, [%4];" \
                 : "=r"(r0), "=r"(r1), "=r"(r2), "=r"(r3) : "r"(addr))

#define MMA_BF16(c, a, b) \
    asm volatile("mma.sync.aligned.m16n8k16.row.col.f32.bf16.bf16.f32 " \
                 "{%0,%1,%2,%3}, {%4,%5,%6,%7}, {%8,%9}, {%0,%1,%2,%3};" \
                 : "+f"((c)[0]), "+f"((c)[1]), "+f"((c)[2]), "+f"((c)[3]) \
                 : "r"((a)[0]), "r"((a)[1]), "r"((a)[2]), "r"((a)[3]), \
                   "r"((b)[0]), "r"((b)[1]))

#define SWZ(x) ((unsigned)(x) ^ (((unsigned)(x) >> 3) & 0x70u))

// ---------------- prep: weight split to bf16 hi/lo + read transpose + deg init ------
__global__ void prep_kernel(const float* __restrict__ We,
                            const float* __restrict__ Wm,
                            const float* __restrict__ Wr)
{
    int idx = blockIdx.x * blockDim.x + threadIdx.x;
    if (idx < 131072) {                       // embed: OUT=128, IN=64, K=1024
        int o = idx >> 10, k = idx & 1023;
        int i = k >> 4, t = (k >> 3) & 1, h = k & 7;
        float v = We[(((t * 128 + o) * 64 + i) << 3) + h];
        __nv_bfloat16 hi = __float2bfloat16_rn(v);
        g_wbh_e[idx] = hi;
        g_wbl_e[idx] = __float2bfloat16_rn(v - __bfloat162float(hi));
        return;
    }
    idx -= 131072;
    if (idx < 3 * 262144) {                   // mp: OUT=128, IN=128, K=2048
        int l = idx / 262144, r = idx % 262144;
        int o = r >> 11, k = r & 2047;
        int i = k >> 4, t = (k >> 3) & 1, h = k & 7;
        float v = Wm[(size_t)l * 262144 + (((t * 128 + o) * 128 + i) << 3) + h];
        __nv_bfloat16 hi = __float2bfloat16_rn(v);
        g_wbh_m[(size_t)l * 262144 + r] = hi;
        g_wbl_m[(size_t)l * 262144 + r] = __float2bfloat16_rn(v - __bfloat162float(hi));
        return;
    }
    idx -= 3 * 262144;
    if (idx < 65536) {                        // readout fp32 transpose: [k][o], OUT=32, IN=128
        int o = idx & 31, k = idx >> 5;
        int i = k >> 4, t = (k >> 3) & 1, h = k & 7;
        g_wtr[idx] = Wr[(((t * 32 + o) * 128 + i) << 3) + h];
        return;
    }
    idx -= 65536;
    if (idx < NN) g_deg[idx] = 1;             // self loop
}

// ---------------- degree / dinv / CSR ----------------
__global__ void deg_count_kernel(const int* __restrict__ ei)
{
    int e = blockIdx.x * blockDim.x + threadIdx.x;
    if (e < EE) atomicAdd(&g_deg[ei[EE + e]], 1);
}
__global__ void dinv_kernel()
{
    int i = blockIdx.x * blockDim.x + threadIdx.x;
    if (i < NN) g_dinv[i] = rsqrtf((float)g_deg[i]);
}
__global__ void scan_kernel()
{
    __shared__ int part[1024];
    int t = threadIdx.x;
    const int seg = (NN + 1023) / 1024;
    int base = t * seg;
    int s = 0;
    for (int j = 0; j < seg; ++j) {
        int i = base + j;
        if (i < NN) s += g_deg[i] - 1;
    }
    part[t] = s;
    __syncthreads();
    for (int d = 1; d < 1024; d <<= 1) {
        int v = (t >= d) ? part[t - d] : 0;
        __syncthreads();
        part[t] += v;
        __syncthreads();
    }
    int run = part[t] - s;
    for (int j = 0; j < seg; ++j) {
        int i = base + j;
        if (i < NN) {
            g_off[i] = run;
            g_cur[i] = run;
            run += g_deg[i] - 1;
        }
    }
    if (t == 1023) g_off[NN] = part[1023];
}
__global__ void fill_kernel(const int* __restrict__ ei)
{
    int e = blockIdx.x * blockDim.x + threadIdx.x;
    if (e >= EE) return;
    int r = ei[e];
    int c = ei[EE + e];
    int pos = atomicAdd(&g_cur[c], 1);
    g_rows[pos] = r;
    g_nrm[pos]  = g_dinv[r] * g_dinv[c];
}

// ---------------- KAN GEMM via mma.sync (legacy HMMA, base-target PTX) --------------
// Y[128-tile, 128] = phi(X) @ W^T, bf16 3-term split (ah*bh + al*bh + ah*bl).
// Block: 128 rows x 128 cols, 512 threads = 16 warps in 4x4 grid, warp tile 32x32.
// K-chunk 64 (4 input dims x 16 trig). SMEM tiles Ah/Al/Bh/Bl 16KB each, SW128 swizzle.
#define DSMEM 65536

template <int INDIM>
__global__ void __launch_bounds__(512) kan_tc(const float* __restrict__ Xext, int sel)
{
    extern __shared__ char smem[];
    const unsigned sb = s2u(smem);
    const unsigned AH = 0, AL = 16384, BH = 32768, BL = 49152;

    const int tid = threadIdx.x, wid = tid >> 5, lane = tid & 31;
    const int rowBase = blockIdx.x * 128;
    const int Ktot = INDIM * 16;
    const int NCHK = INDIM / 4;

    const float* X = (sel == 0) ? Xext : g_h;
    float*       Y = (sel == 0) ? g_h  : g_hk;
    const __nv_bfloat16* WH = (sel == 0) ? g_wbh_e : g_wbh_m + (size_t)(sel - 1) * 262144;
    const __nv_bfloat16* WL = (sel == 0) ? g_wbl_e : g_wbl_m + (size_t)(sel - 1) * 262144;

    // warp coordinates: wm rows (4 x 32), wn cols (4 x 32)
    const int wm = wid & 3;
    const int wn = wid >> 2;

    // ldmatrix raw byte offsets (within a 16KB tile), swizzled per k-step
    // A (row-major m16k16 frags): lanes 0-7 m1 rows0-7/k0-7, 8-15 m2 rows8-15/k0-7,
    //                             16-23 m3 rows0-7/k8-15, 24-31 m4 rows8-15/k8-15
    const int aRow = wm * 32 + (lane & 15);
    const unsigned aColH = ((unsigned)lane >> 4) * 16;
    unsigned aRaw[2];
    aRaw[0] = (unsigned)aRow * 128 + aColH;
    aRaw[1] = (unsigned)(aRow + 16) * 128 + aColH;
    // B stored [n][k]: x4 covers 2 n-tiles: m1 nt0/k0-7, m2 nt0/k8-15, m3 nt1/k0-7, m4 nt1/k8-15
    const int bRow = wn * 32 + ((lane >> 4) & 1) * 8 + (lane & 7);
    const unsigned bColH = (((unsigned)lane >> 3) & 1) * 16;
    unsigned bRaw[2];
    bRaw[0] = (unsigned)bRow * 128 + bColH;
    bRaw[1] = (unsigned)(bRow + 16) * 128 + bColH;

    float acc[2][4][4];
#pragma unroll
    for (int i = 0; i < 2; ++i)
#pragma unroll
        for (int j = 0; j < 4; ++j)
#pragma unroll
            for (int q = 0; q < 4; ++q) acc[i][j][q] = 0.f;

    for (int ch = 0; ch < NCHK; ++ch) {
        __syncthreads();
        // ---- phi tile: 128 rows x 64 k (4 dims x 16 trig), bf16 hi/lo, swizzled ----
        {
            int row = tid & 127, d = tid >> 7;        // one (row, dim) per thread
            int r = rowBase + row;
            float x = 0.f;
            if (r < NN) x = X[(size_t)r * INDIM + ch * 4 + d];
            float s1, c1;
            __sincosf(x, &s1, &c1);
            float ck = c1, sk = s1;
            union { __nv_bfloat16 b[8]; uint4 u; } chv, clv, shv, slv;
#pragma unroll
            for (int hh = 0; hh < 8; ++hh) {
                __nv_bfloat16 bh_ = __float2bfloat16_rn(ck);
                chv.b[hh] = bh_;
                clv.b[hh] = __float2bfloat16_rn(ck - __bfloat162float(bh_));
                __nv_bfloat16 bs_ = __float2bfloat16_rn(sk);
                shv.b[hh] = bs_;
                slv.b[hh] = __float2bfloat16_rn(sk - __bfloat162float(bs_));
                float cn = ck * c1 - sk * s1;
                sk = sk * c1 + ck * s1;
                ck = cn;
            }
            unsigned oc = SWZ(row * 128 + d * 32);
            unsigned os = SWZ(row * 128 + d * 32 + 16);
            *(uint4*)(smem + AH + oc) = chv.u;
            *(uint4*)(smem + AH + os) = shv.u;
            *(uint4*)(smem + AL + oc) = clv.u;
            *(uint4*)(smem + AL + os) = slv.u;
        }
        // ---- B tiles: 128 n-rows x 64 k, hi+lo, coalesced GMEM -> swizzled SMEM ----
        {
            int k0 = ch * 64;
#pragma unroll
            for (int j = 0; j < 2; ++j) {
                int idx = tid + 512 * j;              // 1024 16B units per tile
                int o = idx >> 3, u = idx & 7;
                unsigned so = SWZ(o * 128 + u * 16);
                *(uint4*)(smem + BH + so) = *(const uint4*)(WH + (size_t)o * Ktot + k0 + u * 8);
                *(uint4*)(smem + BL + so) = *(const uint4*)(WL + (size_t)o * Ktot + k0 + u * 8);
            }
        }
        __syncthreads();

        // ---- compute: 4 k-steps of 16; 3 split terms ----
#pragma unroll
        for (int s = 0; s < 4; ++s) {
            unsigned ah[2][4], al[2][4], bh[4][2], bl[4][2];
#pragma unroll
            for (int mt = 0; mt < 2; ++mt) {
                unsigned off = SWZ(aRaw[mt] + s * 32);
                LDSM4(ah[mt][0], ah[mt][1], ah[mt][2], ah[mt][3], sb + AH + off);
                LDSM4(al[mt][0], al[mt][1], al[mt][2], al[mt][3], sb + AL + off);
            }
#pragma unroll
            for (int p = 0; p < 2; ++p) {
                unsigned off = SWZ(bRaw[p] + s * 32);
                LDSM4(bh[2 * p][0], bh[2 * p][1], bh[2 * p + 1][0], bh[2 * p + 1][1], sb + BH + off);
                LDSM4(bl[2 * p][0], bl[2 * p][1], bl[2 * p + 1][0], bl[2 * p + 1][1], sb + BL + off);
            }
#pragma unroll
            for (int mt = 0; mt < 2; ++mt)
#pragma unroll
                for (int nt = 0; nt < 4; ++nt) {
                    MMA_BF16(acc[mt][nt], ah[mt], bh[nt]);
                    MMA_BF16(acc[mt][nt], al[mt], bh[nt]);
                    MMA_BF16(acc[mt][nt], ah[mt], bl[nt]);
                }
        }
    }

    // ---- epilogue: fragment -> gmem (float2 per row) ----
    const int gid = lane >> 2, tig = lane & 3;
#pragma unroll
    for (int mt = 0; mt < 2; ++mt)
#pragma unroll
        for (int nt = 0; nt < 4; ++nt) {
            int r0  = rowBase + wm * 32 + mt * 16 + gid;
            int col = wn * 32 + nt * 8 + tig * 2;
            if (r0 < NN)
                *(float2*)(Y + (size_t)r0 * 128 + col) =
                    make_float2(acc[mt][nt][0], acc[mt][nt][1]);
            if (r0 + 8 < NN)
                *(float2*)(Y + (size_t)(r0 + 8) * 128 + col) =
                    make_float2(acc[mt][nt][2], acc[mt][nt][3]);
        }
}

// ---------------- aggregation (CSR gather-sum, one warp per node) ----------------
__global__ void agg_kernel()
{
    int w    = (blockIdx.x * blockDim.x + threadIdx.x) >> 5;
    int lane = threadIdx.x & 31;
    if (w >= NN) return;

    float di = g_dinv[w];
    const float4* hk4 = (const float4*)g_hk;
    float4 v = hk4[(size_t)w * 32 + lane];
    float dd = di * di;
    float4 acc = make_float4(dd * v.x, dd * v.y, dd * v.z, dd * v.w);

    int s = g_off[w], e = g_off[w + 1];
    for (int idx = s; idx < e; ++idx) {
        int   r  = g_rows[idx];
        float nm = g_nrm[idx];
        float4 u = hk4[(size_t)r * 32 + lane];
        acc.x = fmaf(nm, u.x, acc.x);
        acc.y = fmaf(nm, u.y, acc.y);
        acc.z = fmaf(nm, u.z, acc.z);
        acc.w = fmaf(nm, u.w, acc.w);
    }
    ((float4*)g_h)[(size_t)w * 32 + lane] = acc;
}

// ---------------- mean pool (batch sorted) ----------------
__global__ void pool_kernel(const int* __restrict__ batch)
{
    int g = blockIdx.x;
    int f = threadIdx.x;

    int lo = 0, hi = NN;
    while (lo < hi) { int m = (lo + hi) >> 1; if (batch[m] < g) lo = m + 1; else hi = m; }
    int st = lo;
    lo = 0; hi = NN;
    while (lo < hi) { int m = (lo + hi) >> 1; if (batch[m] < g + 1) lo = m + 1; else hi = m; }
    int en = lo;

    float acc = 0.f;
    for (int n = st; n < en; ++n) acc += g_h[(size_t)n * 128 + f];
    float cnt = (float)(en - st);
    g_pool[g * 128 + f] = acc / fmaxf(cnt, 1.0f);
}

// ---------------- readout (fp32) ----------------
__global__ void read_kernel(float* __restrict__ out)
{
    __shared__ float phi[2048];
    __shared__ float part[32 * 8];
    int g   = blockIdx.x;
    int tid = threadIdx.x;

    if (tid < 128) {
        float x = g_pool[g * 128 + tid];
        float s1, c1;
        sincosf(x, &s1, &c1);
        float ck = c1, sk = s1;
#pragma unroll
        for (int hh = 0; hh < 8; ++hh) {
            phi[tid * 16 + hh]     = ck;
            phi[tid * 16 + 8 + hh] = sk;
            float cn = ck * c1 - sk * s1;
            sk = sk * c1 + ck * s1;
            ck = cn;
        }
    }
    __syncthreads();

    int o = tid >> 3, sg = tid & 7;
    float acc = 0.f;
    int k0 = sg * 256;
    for (int k = k0; k < k0 + 256; ++k)
        acc = fmaf(phi[k], g_wtr[k * 32 + o], acc);
    part[o * 8 + sg] = acc;
    __syncthreads();

    if (tid < 32) {
        float s = 0.f;
#pragma unroll
        for (int j = 0; j < 8; ++j) s += part[tid * 8 + j];
        out[g * 32 + tid] = s;
    }
}

// ---------------- launch ----------------
extern "C" void kernel_launch(void* const* d_in, const int* in_sizes, int n_in,
                              void* d_out, int out_size)
{
    const float* features = (const float*)d_in[0];
    const int*   ei       = (const int*)  d_in[1];
    const int*   batch    = (const int*)  d_in[2];
    const float* W_embed  = (const float*)d_in[3];
    const float* W_mp     = (const float*)d_in[4];
    const float* W_read   = (const float*)d_in[5];
    float* out = (float*)d_out;

    cudaFuncSetAttribute(kan_tc<64>,  cudaFuncAttributeMaxDynamicSharedMemorySize, DSMEM);
    cudaFuncSetAttribute(kan_tc<128>, cudaFuncAttributeMaxDynamicSharedMemorySize, DSMEM);

    // 1. prep (weight split + read transpose + deg init)
    const int PREP = 131072 + 3 * 262144 + 65536 + NN;
    prep_kernel<<<(PREP + 255) / 256, 256>>>(W_embed, W_mp, W_read);

    // 2. degrees + CSR
    deg_count_kernel<<<(EE + 255) / 256, 256>>>(ei);
    dinv_kernel     <<<(NN + 255) / 256, 256>>>();
    scan_kernel<<<1, 1024>>>();
    fill_kernel<<<(EE + 255) / 256, 256>>>(ei);

    // 3. embed + mp layers
    const int GK = (NN + 127) / 128;   // 391 tiles
    kan_tc<64><<<GK, 512, DSMEM>>>(features, 0);
    for (int l = 0; l < NL; ++l) {
        kan_tc<128><<<GK, 512, DSMEM>>>(features, l + 1);
        agg_kernel<<<(NN * 32 + 255) / 256, 256>>>();
    }

    // 4. pool + readout
    pool_kernel<<<NG, 128>>>(batch);
    read_kernel<<<NG, 256>>>(out);
}

// round 14
// speedup vs baseline: 2.3473x; 1.0791x over previous
#include <cuda_runtime.h>
#include <cuda_bf16.h>
#include <cstdint>
#include <stdint.h>
#include <math.h>

// Problem constants
#define NN   50000
#define EE   1600000
#define INF  64
#define HIDF 128
#define NG   64
#define NL   3
#define NB   196      // scan blocks: ceil(NN/256)

// ---------------- scratch (__device__ globals; no runtime allocation) ----------------
__device__ float g_h [NN * HIDF];
__device__ float g_hk[NN * HIDF];
__device__ int   g_deg [NN];
__device__ float g_dinv[NN];
__device__ int   g_off [NN + 1];
__device__ int   g_cur [NN];
__device__ int   g_part[256];
__device__ int   g_rows[EE];
__device__ float g_nrm [EE];
__device__ __nv_bfloat16 g_wbh_e[128 * 1024];       // embed W hi, [o][k]
__device__ __nv_bfloat16 g_wbl_e[128 * 1024];       // embed W lo
__device__ __nv_bfloat16 g_wbh_m[3 * 128 * 2048];   // mp W hi, [l][o][k]
__device__ __nv_bfloat16 g_wbl_m[3 * 128 * 2048];   // mp W lo
__device__ float g_wtr [2048 * 32];                 // readout W fp32, [k][o]
__device__ float g_pool[NG * HIDF];

// ---------------- PTX helpers (base-target legal: ldmatrix + mma.sync) ----------------
__device__ __forceinline__ unsigned s2u(const void* p)
{
    unsigned a;
    asm("{ .reg .u64 t; cvta.to.shared.u64 t, %1; cvt.u32.u64 %0, t; }" : "=r"(a) : "l"(p));
    return a;
}

#define LDSM4(r0, r1, r2, r3, addr) \
    asm volatile("ldmatrix.sync.aligned.m8n8.x4.shared.b16 {%0,%1,%2,%3}, [%4];" \
                 : "=r"(r0), "=r"(r1), "=r"(r2), "=r"(r3) : "r"(addr))

#define MMA_BF16(c, a, b) \
    asm volatile("mma.sync.aligned.m16n8k16.row.col.f32.bf16.bf16.f32 " \
                 "{%0,%1,%2,%3}, {%4,%5,%6,%7}, {%8,%9}, {%0,%1,%2,%3};" \
                 : "+f"((c)[0]), "+f"((c)[1]), "+f"((c)[2]), "+f"((c)[3]) \
                 : "r"((a)[0]), "r"((a)[1]), "r"((a)[2]), "r"((a)[3]), \
                   "r"((b)[0]), "r"((b)[1]))

// pack: result lo16 = hi-half of a, hi16 = hi-half of b
#define PACKHI(d, a, b) \
    asm("prmt.b32 %0, %1, %2, 0x7632;" : "=r"(d) : "r"(a), "r"(b))
// pack two fp32 lo-residuals to bf16x2: first PTX src -> high half
#define PACKLO(d, fb, fa) \
    asm("cvt.rn.bf16x2.f32 %0, %1, %2;" : "=r"(d) : "f"(fb), "f"(fa))

#define SWZ(x) ((unsigned)(x) ^ (((unsigned)(x) >> 3) & 0x70u))

// ---------------- prep: weight split to bf16 hi/lo + read transpose + deg init ------
__global__ void prep_kernel(const float* __restrict__ We,
                            const float* __restrict__ Wm,
                            const float* __restrict__ Wr)
{
    int idx = blockIdx.x * blockDim.x + threadIdx.x;
    if (idx < 131072) {                       // embed: OUT=128, IN=64, K=1024
        int o = idx >> 10, k = idx & 1023;
        int i = k >> 4, t = (k >> 3) & 1, h = k & 7;
        float v = We[(((t * 128 + o) * 64 + i) << 3) + h];
        __nv_bfloat16 hi = __float2bfloat16_rn(v);
        g_wbh_e[idx] = hi;
        g_wbl_e[idx] = __float2bfloat16_rn(v - __bfloat162float(hi));
        return;
    }
    idx -= 131072;
    if (idx < 3 * 262144) {                   // mp: OUT=128, IN=128, K=2048
        int l = idx / 262144, r = idx % 262144;
        int o = r >> 11, k = r & 2047;
        int i = k >> 4, t = (k >> 3) & 1, h = k & 7;
        float v = Wm[(size_t)l * 262144 + (((t * 128 + o) * 128 + i) << 3) + h];
        __nv_bfloat16 hi = __float2bfloat16_rn(v);
        g_wbh_m[(size_t)l * 262144 + r] = hi;
        g_wbl_m[(size_t)l * 262144 + r] = __float2bfloat16_rn(v - __bfloat162float(hi));
        return;
    }
    idx -= 3 * 262144;
    if (idx < 65536) {                        // readout fp32 transpose: [k][o], OUT=32, IN=128
        int o = idx & 31, k = idx >> 5;
        int i = k >> 4, t = (k >> 3) & 1, h = k & 7;
        g_wtr[idx] = Wr[(((t * 32 + o) * 128 + i) << 3) + h];
        return;
    }
    idx -= 65536;
    if (idx < NN) g_deg[idx] = 1;             // self loop
}

// ---------------- degree / dinv ----------------
__global__ void deg_count_kernel(const int* __restrict__ ei)
{
    int e = blockIdx.x * blockDim.x + threadIdx.x;
    if (e < EE) atomicAdd(&g_deg[ei[EE + e]], 1);
}
__global__ void dinv_kernel()
{
    int i = blockIdx.x * blockDim.x + threadIdx.x;
    if (i < NN) g_dinv[i] = rsqrtf((float)g_deg[i]);
}

// ---------------- parallel CSR scan: 3 small kernels ----------------
__global__ void scan1_kernel()        // NB blocks x 256: block partial sums of (deg-1)
{
    __shared__ int sm[256];
    int t = threadIdx.x;
    int i = blockIdx.x * 256 + t;
    sm[t] = (i < NN) ? g_deg[i] - 1 : 0;
    __syncthreads();
#pragma unroll
    for (int d = 128; d > 0; d >>= 1) {
        if (t < d) sm[t] += sm[t + d];
        __syncthreads();
    }
    if (t == 0) g_part[blockIdx.x] = sm[0];
}
__global__ void scan2_kernel()        // 1 block x 256: exclusive scan of NB partials
{
    __shared__ int sm[256];
    int t = threadIdx.x;
    int v = (t < NB) ? g_part[t] : 0;
    sm[t] = v;
    __syncthreads();
#pragma unroll
    for (int d = 1; d < 256; d <<= 1) {
        int u = (t >= d) ? sm[t - d] : 0;
        __syncthreads();
        sm[t] += u;
        __syncthreads();
    }
    if (t < NB) g_part[t] = sm[t] - v;      // exclusive prefix
    if (t == 0) g_off[NN] = EE;
}
__global__ void scan3_kernel()        // NB blocks x 256: per-node offsets
{
    __shared__ int sm[256];
    int t = threadIdx.x;
    int i = blockIdx.x * 256 + t;
    int v = (i < NN) ? g_deg[i] - 1 : 0;
    sm[t] = v;
    __syncthreads();
#pragma unroll
    for (int d = 1; d < 256; d <<= 1) {
        int u = (t >= d) ? sm[t - d] : 0;
        __syncthreads();
        sm[t] += u;
        __syncthreads();
    }
    if (i < NN) {
        int off = g_part[blockIdx.x] + sm[t] - v;
        g_off[i] = off;
        g_cur[i] = off;
    }
}

__global__ void fill_kernel(const int* __restrict__ ei)
{
    int e = blockIdx.x * blockDim.x + threadIdx.x;
    if (e >= EE) return;
    int r = ei[e];
    int c = ei[EE + e];
    int pos = atomicAdd(&g_cur[c], 1);
    g_rows[pos] = r;
    g_nrm[pos]  = g_dinv[r] * g_dinv[c];
}

// ---------------- KAN GEMM via mma.sync (legacy HMMA, base-target PTX) --------------
// Y[128-tile, 128] = phi(X) @ W^T, bf16 3-term split (ah*bh + al*bh + ah*bl).
// Block: 128 rows x 128 cols, 512 threads = 16 warps in 4x4 grid, warp tile 32x32.
// K-chunk 64 (4 input dims x 16 trig). SMEM tiles Ah/Al/Bh/Bl 16KB each, SW128 swizzle.
#define DSMEM 65536

template <int INDIM>
__global__ void __launch_bounds__(512) kan_tc(const float* __restrict__ Xext, int sel)
{
    extern __shared__ char smem[];
    const unsigned sb = s2u(smem);
    const unsigned AH = 0, AL = 16384, BH = 32768, BL = 49152;

    const int tid = threadIdx.x, wid = tid >> 5, lane = tid & 31;
    const int rowBase = blockIdx.x * 128;
    const int Ktot = INDIM * 16;
    const int NCHK = INDIM / 4;

    const float* X = (sel == 0) ? Xext : g_h;
    float*       Y = (sel == 0) ? g_h  : g_hk;
    const __nv_bfloat16* WH = (sel == 0) ? g_wbh_e : g_wbh_m + (size_t)(sel - 1) * 262144;
    const __nv_bfloat16* WL = (sel == 0) ? g_wbl_e : g_wbl_m + (size_t)(sel - 1) * 262144;

    const int wm = wid & 3;
    const int wn = wid >> 2;

    // ldmatrix raw byte offsets (within a 16KB tile), swizzled per k-step
    const int aRow = wm * 32 + (lane & 15);
    const unsigned aColH = ((unsigned)lane >> 4) * 16;
    unsigned aRaw[2];
    aRaw[0] = (unsigned)aRow * 128 + aColH;
    aRaw[1] = (unsigned)(aRow + 16) * 128 + aColH;
    const int bRow = wn * 32 + ((lane >> 4) & 1) * 8 + (lane & 7);
    const unsigned bColH = (((unsigned)lane >> 3) & 1) * 16;
    unsigned bRaw[2];
    bRaw[0] = (unsigned)bRow * 128 + bColH;
    bRaw[1] = (unsigned)(bRow + 16) * 128 + bColH;

    float acc[2][4][4];
#pragma unroll
    for (int i = 0; i < 2; ++i)
#pragma unroll
        for (int j = 0; j < 4; ++j)
#pragma unroll
            for (int q = 0; q < 4; ++q) acc[i][j][q] = 0.f;

    for (int ch = 0; ch < NCHK; ++ch) {
        __syncthreads();
        // ---- phi tile: 128 rows x 64 k, truncation hi/lo split, PRMT/bf16x2 packed ----
        {
            int row = tid & 127, d = tid >> 7;        // one (row, dim) per thread
            int r = rowBase + row;
            float x = 0.f;
            if (r < NN) x = X[(size_t)r * INDIM + ch * 4 + d];
            float s1, c1;
            __sincosf(x, &s1, &c1);
            float ck = c1, sk = s1;
            unsigned chi[4], clo[4], shi[4], slo[4];
#pragma unroll
            for (int p = 0; p < 4; ++p) {
                float ca = ck, sa = sk;
                float cn = ck * c1 - sk * s1;
                sk = sk * c1 + ck * s1;
                ck = cn;
                float cb = ck, sb2 = sk;
                cn = ck * c1 - sk * s1;
                sk = sk * c1 + ck * s1;
                ck = cn;
                unsigned cau = __float_as_uint(ca), cbu = __float_as_uint(cb);
                unsigned sau = __float_as_uint(sa), sbu = __float_as_uint(sb2);
                PACKHI(chi[p], cau, cbu);
                PACKHI(shi[p], sau, sbu);
                float cah = __uint_as_float(cau & 0xFFFF0000u);
                float cbh = __uint_as_float(cbu & 0xFFFF0000u);
                float sah = __uint_as_float(sau & 0xFFFF0000u);
                float sbh = __uint_as_float(sbu & 0xFFFF0000u);
                PACKLO(clo[p], cb - cbh, ca - cah);
                PACKLO(slo[p], sb2 - sbh, sa - sah);
            }
            unsigned oc = SWZ(row * 128 + d * 32);
            unsigned os = SWZ(row * 128 + d * 32 + 16);
            *(uint4*)(smem + AH + oc) = make_uint4(chi[0], chi[1], chi[2], chi[3]);
            *(uint4*)(smem + AH + os) = make_uint4(shi[0], shi[1], shi[2], shi[3]);
            *(uint4*)(smem + AL + oc) = make_uint4(clo[0], clo[1], clo[2], clo[3]);
            *(uint4*)(smem + AL + os) = make_uint4(slo[0], slo[1], slo[2], slo[3]);
        }
        // ---- B tiles: 128 n-rows x 64 k, hi+lo, coalesced GMEM -> swizzled SMEM ----
        {
            int k0 = ch * 64;
#pragma unroll
            for (int j = 0; j < 2; ++j) {
                int idx = tid + 512 * j;              // 1024 16B units per tile
                int o = idx >> 3, u = idx & 7;
                unsigned so = SWZ(o * 128 + u * 16);
                *(uint4*)(smem + BH + so) = *(const uint4*)(WH + (size_t)o * Ktot + k0 + u * 8);
                *(uint4*)(smem + BL + so) = *(const uint4*)(WL + (size_t)o * Ktot + k0 + u * 8);
            }
        }
        __syncthreads();

        // ---- compute: 4 k-steps of 16; 3 split terms ----
#pragma unroll
        for (int s = 0; s < 4; ++s) {
            unsigned ah[2][4], al[2][4], bh[4][2], bl[4][2];
#pragma unroll
            for (int mt = 0; mt < 2; ++mt) {
                unsigned off = SWZ(aRaw[mt] + s * 32);
                LDSM4(ah[mt][0], ah[mt][1], ah[mt][2], ah[mt][3], sb + AH + off);
                LDSM4(al[mt][0], al[mt][1], al[mt][2], al[mt][3], sb + AL + off);
            }
#pragma unroll
            for (int p = 0; p < 2; ++p) {
                unsigned off = SWZ(bRaw[p] + s * 32);
                LDSM4(bh[2 * p][0], bh[2 * p][1], bh[2 * p + 1][0], bh[2 * p + 1][1], sb + BH + off);
                LDSM4(bl[2 * p][0], bl[2 * p][1], bl[2 * p + 1][0], bl[2 * p + 1][1], sb + BL + off);
            }
#pragma unroll
            for (int mt = 0; mt < 2; ++mt)
#pragma unroll
                for (int nt = 0; nt < 4; ++nt) {
                    MMA_BF16(acc[mt][nt], ah[mt], bh[nt]);
                    MMA_BF16(acc[mt][nt], al[mt], bh[nt]);
                    MMA_BF16(acc[mt][nt], ah[mt], bl[nt]);
                }
        }
    }

    // ---- epilogue: fragment -> gmem (float2 per row) ----
    const int gid = lane >> 2, tig = lane & 3;
#pragma unroll
    for (int mt = 0; mt < 2; ++mt)
#pragma unroll
        for (int nt = 0; nt < 4; ++nt) {
            int r0  = rowBase + wm * 32 + mt * 16 + gid;
            int col = wn * 32 + nt * 8 + tig * 2;
            if (r0 < NN)
                *(float2*)(Y + (size_t)r0 * 128 + col) =
                    make_float2(acc[mt][nt][0], acc[mt][nt][1]);
            if (r0 + 8 < NN)
                *(float2*)(Y + (size_t)(r0 + 8) * 128 + col) =
                    make_float2(acc[mt][nt][2], acc[mt][nt][3]);
        }
}

// ---------------- aggregation (CSR gather-sum, one warp per node, MLP=4) -------------
__global__ void agg_kernel()
{
    int w    = (blockIdx.x * blockDim.x + threadIdx.x) >> 5;
    int lane = threadIdx.x & 31;
    if (w >= NN) return;

    float di = g_dinv[w];
    const float4* hk4 = (const float4*)g_hk;
    float4 v = hk4[(size_t)w * 32 + lane];
    float dd = di * di;
    float4 acc = make_float4(dd * v.x, dd * v.y, dd * v.z, dd * v.w);

    int s = g_off[w], e = g_off[w + 1];
    int idx = s;
    for (; idx + 4 <= e; idx += 4) {
        int   r0 = g_rows[idx],     r1 = g_rows[idx + 1];
        int   r2 = g_rows[idx + 2], r3 = g_rows[idx + 3];
        float n0 = g_nrm[idx],      n1 = g_nrm[idx + 1];
        float n2 = g_nrm[idx + 2],  n3 = g_nrm[idx + 3];
        float4 u0 = hk4[(size_t)r0 * 32 + lane];
        float4 u1 = hk4[(size_t)r1 * 32 + lane];
        float4 u2 = hk4[(size_t)r2 * 32 + lane];
        float4 u3 = hk4[(size_t)r3 * 32 + lane];
        acc.x = fmaf(n0, u0.x, acc.x); acc.y = fmaf(n0, u0.y, acc.y);
        acc.z = fmaf(n0, u0.z, acc.z); acc.w = fmaf(n0, u0.w, acc.w);
        acc.x = fmaf(n1, u1.x, acc.x); acc.y = fmaf(n1, u1.y, acc.y);
        acc.z = fmaf(n1, u1.z, acc.z); acc.w = fmaf(n1, u1.w, acc.w);
        acc.x = fmaf(n2, u2.x, acc.x); acc.y = fmaf(n2, u2.y, acc.y);
        acc.z = fmaf(n2, u2.z, acc.z); acc.w = fmaf(n2, u2.w, acc.w);
        acc.x = fmaf(n3, u3.x, acc.x); acc.y = fmaf(n3, u3.y, acc.y);
        acc.z = fmaf(n3, u3.z, acc.z); acc.w = fmaf(n3, u3.w, acc.w);
    }
    for (; idx < e; ++idx) {
        int   r  = g_rows[idx];
        float nm = g_nrm[idx];
        float4 u = hk4[(size_t)r * 32 + lane];
        acc.x = fmaf(nm, u.x, acc.x);
        acc.y = fmaf(nm, u.y, acc.y);
        acc.z = fmaf(nm, u.z, acc.z);
        acc.w = fmaf(nm, u.w, acc.w);
    }
    ((float4*)g_h)[(size_t)w * 32 + lane] = acc;
}

// ---------------- mean pool (batch sorted) ----------------
__global__ void pool_kernel(const int* __restrict__ batch)
{
    int g = blockIdx.x;
    int f = threadIdx.x;

    int lo = 0, hi = NN;
    while (lo < hi) { int m = (lo + hi) >> 1; if (batch[m] < g) lo = m + 1; else hi = m; }
    int st = lo;
    lo = 0; hi = NN;
    while (lo < hi) { int m = (lo + hi) >> 1; if (batch[m] < g + 1) lo = m + 1; else hi = m; }
    int en = lo;

    float acc = 0.f;
    for (int n = st; n < en; ++n) acc += g_h[(size_t)n * 128 + f];
    float cnt = (float)(en - st);
    g_pool[g * 128 + f] = acc / fmaxf(cnt, 1.0f);
}

// ---------------- readout (fp32) ----------------
__global__ void read_kernel(float* __restrict__ out)
{
    __shared__ float phi[2048];
    __shared__ float part[32 * 8];
    int g   = blockIdx.x;
    int tid = threadIdx.x;

    if (tid < 128) {
        float x = g_pool[g * 128 + tid];
        float s1, c1;
        sincosf(x, &s1, &c1);
        float ck = c1, sk = s1;
#pragma unroll
        for (int hh = 0; hh < 8; ++hh) {
            phi[tid * 16 + hh]     = ck;
            phi[tid * 16 + 8 + hh] = sk;
            float cn = ck * c1 - sk * s1;
            sk = sk * c1 + ck * s1;
            ck = cn;
        }
    }
    __syncthreads();

    int o = tid >> 3, sg = tid & 7;
    float acc = 0.f;
    int k0 = sg * 256;
    for (int k = k0; k < k0 + 256; ++k)
        acc = fmaf(phi[k], g_wtr[k * 32 + o], acc);
    part[o * 8 + sg] = acc;
    __syncthreads();

    if (tid < 32) {
        float s = 0.f;
#pragma unroll
        for (int j = 0; j < 8; ++j) s += part[tid * 8 + j];
        out[g * 32 + tid] = s;
    }
}

// ---------------- launch ----------------
extern "C" void kernel_launch(void* const* d_in, const int* in_sizes, int n_in,
                              void* d_out, int out_size)
{
    const float* features = (const float*)d_in[0];
    const int*   ei       = (const int*)  d_in[1];
    const int*   batch    = (const int*)  d_in[2];
    const float* W_embed  = (const float*)d_in[3];
    const float* W_mp     = (const float*)d_in[4];
    const float* W_read   = (const float*)d_in[5];
    float* out = (float*)d_out;

    cudaFuncSetAttribute(kan_tc<64>,  cudaFuncAttributeMaxDynamicSharedMemorySize, DSMEM);
    cudaFuncSetAttribute(kan_tc<128>, cudaFuncAttributeMaxDynamicSharedMemorySize, DSMEM);

    // 1. prep (weight split + read transpose + deg init)
    const int PREP = 131072 + 3 * 262144 + 65536 + NN;
    prep_kernel<<<(PREP + 255) / 256, 256>>>(W_embed, W_mp, W_read);

    // 2. degrees + CSR (parallel scan)
    deg_count_kernel<<<(EE + 255) / 256, 256>>>(ei);
    dinv_kernel     <<<(NN + 255) / 256, 256>>>();
    scan1_kernel<<<NB, 256>>>();
    scan2_kernel<<<1, 256>>>();
    scan3_kernel<<<NB, 256>>>();
    fill_kernel<<<(EE + 255) / 256, 256>>>(ei);

    // 3. embed + mp layers
    const int GK = (NN + 127) / 128;   // 391 tiles
    kan_tc<64><<<GK, 512, DSMEM>>>(features, 0);
    for (int l = 0; l < NL; ++l) {
        kan_tc<128><<<GK, 512, DSMEM>>>(features, l + 1);
        agg_kernel<<<(NN * 32 + 255) / 256, 256>>>();
    }

    // 4. pool + readout
    pool_kernel<<<NG, 128>>>(batch);
    read_kernel<<<NG, 256>>>(out);
}

// round 15
// speedup vs baseline: 2.4563x; 1.0465x over previous
#include <cuda_runtime.h>
#include <cuda_bf16.h>
#include <cstdint>
#include <stdint.h>
#include <math.h>

// Problem constants
#define NN   50000
#define EE   1600000
#define INF  64
#define HIDF 128
#define NG   64
#define NL   3
#define NB   196      // scan blocks: ceil(NN/256)

// ---------------- scratch (__device__ globals; no runtime allocation) ----------------
__device__ float g_h [NN * HIDF];
__device__ float g_hk[NN * HIDF];
__device__ int   g_deg [NN];
__device__ float g_dinv[NN];
__device__ int   g_off [NN + 1];
__device__ int   g_cur [NN];
__device__ int   g_part[256];
__device__ int   g_rows[EE];
__device__ float g_nrm [EE];
__device__ __nv_bfloat16 g_wbh_e[128 * 1024];       // embed W hi, [o][k]
__device__ __nv_bfloat16 g_wbl_e[128 * 1024];       // embed W lo
__device__ __nv_bfloat16 g_wbh_m[3 * 128 * 2048];   // mp W hi, [l][o][k]
__device__ __nv_bfloat16 g_wbl_m[3 * 128 * 2048];   // mp W lo
__device__ float g_wtr [2048 * 32];                 // readout W fp32, [k][o]
__device__ float g_pool[NG * HIDF];

// ---------------- PTX helpers (base-target legal) ----------------
__device__ __forceinline__ unsigned s2u(const void* p)
{
    unsigned a;
    asm("{ .reg .u64 t; cvta.to.shared.u64 t, %1; cvt.u32.u64 %0, t; }" : "=r"(a) : "l"(p));
    return a;
}

#define LDSM4(r0, r1, r2, r3, addr) \
    asm volatile("ldmatrix.sync.aligned.m8n8.x4.shared.b16 {%0,%1,%2,%3}, [%4];" \
                 : "=r"(r0), "=r"(r1), "=r"(r2), "=r"(r3) : "r"(addr))

#define MMA_BF16(c, a, b) \
    asm volatile("mma.sync.aligned.m16n8k16.row.col.f32.bf16.bf16.f32 " \
                 "{%0,%1,%2,%3}, {%4,%5,%6,%7}, {%8,%9}, {%0,%1,%2,%3};" \
                 : "+f"((c)[0]), "+f"((c)[1]), "+f"((c)[2]), "+f"((c)[3]) \
                 : "r"((a)[0]), "r"((a)[1]), "r"((a)[2]), "r"((a)[3]), \
                   "r"((b)[0]), "r"((b)[1]))

#define PACKHI(d, a, b) \
    asm("prmt.b32 %0, %1, %2, 0x7632;" : "=r"(d) : "r"(a), "r"(b))
#define PACKLO(d, fb, fa) \
    asm("cvt.rn.bf16x2.f32 %0, %1, %2;" : "=r"(d) : "f"(fb), "f"(fa))

#define CPASYNC16(sa, ga) \
    asm volatile("cp.async.cg.shared.global [%0], [%1], 16;" :: "r"(sa), "l"(ga))
#define CPCOMMIT() asm volatile("cp.async.commit_group;" ::: "memory")
#define CPWAIT0()  asm volatile("cp.async.wait_group 0;" ::: "memory")

#define SWZ(x) ((unsigned)(x) ^ (((unsigned)(x) >> 3) & 0x70u))

// ---------------- prep: weight split to bf16 hi/lo + read transpose + deg init ------
__global__ void prep_kernel(const float* __restrict__ We,
                            const float* __restrict__ Wm,
                            const float* __restrict__ Wr)
{
    int idx = blockIdx.x * blockDim.x + threadIdx.x;
    if (idx < 131072) {                       // embed: OUT=128, IN=64, K=1024
        int o = idx >> 10, k = idx & 1023;
        int i = k >> 4, t = (k >> 3) & 1, h = k & 7;
        float v = We[(((t * 128 + o) * 64 + i) << 3) + h];
        __nv_bfloat16 hi = __float2bfloat16_rn(v);
        g_wbh_e[idx] = hi;
        g_wbl_e[idx] = __float2bfloat16_rn(v - __bfloat162float(hi));
        return;
    }
    idx -= 131072;
    if (idx < 3 * 262144) {                   // mp: OUT=128, IN=128, K=2048
        int l = idx / 262144, r = idx % 262144;
        int o = r >> 11, k = r & 2047;
        int i = k >> 4, t = (k >> 3) & 1, h = k & 7;
        float v = Wm[(size_t)l * 262144 + (((t * 128 + o) * 128 + i) << 3) + h];
        __nv_bfloat16 hi = __float2bfloat16_rn(v);
        g_wbh_m[(size_t)l * 262144 + r] = hi;
        g_wbl_m[(size_t)l * 262144 + r] = __float2bfloat16_rn(v - __bfloat162float(hi));
        return;
    }
    idx -= 3 * 262144;
    if (idx < 65536) {                        // readout fp32 transpose: [k][o], OUT=32, IN=128
        int o = idx & 31, k = idx >> 5;
        int i = k >> 4, t = (k >> 3) & 1, h = k & 7;
        g_wtr[idx] = Wr[(((t * 32 + o) * 128 + i) << 3) + h];
        return;
    }
    idx -= 65536;
    if (idx < NN) g_deg[idx] = 1;             // self loop
}

// ---------------- degree / dinv ----------------
__global__ void deg_count_kernel(const int* __restrict__ ei)
{
    int e = blockIdx.x * blockDim.x + threadIdx.x;
    if (e < EE) atomicAdd(&g_deg[ei[EE + e]], 1);
}
__global__ void dinv_kernel()
{
    int i = blockIdx.x * blockDim.x + threadIdx.x;
    if (i < NN) g_dinv[i] = rsqrtf((float)g_deg[i]);
}

// ---------------- parallel CSR scan: 3 small kernels ----------------
__global__ void scan1_kernel()
{
    __shared__ int sm[256];
    int t = threadIdx.x;
    int i = blockIdx.x * 256 + t;
    sm[t] = (i < NN) ? g_deg[i] - 1 : 0;
    __syncthreads();
#pragma unroll
    for (int d = 128; d > 0; d >>= 1) {
        if (t < d) sm[t] += sm[t + d];
        __syncthreads();
    }
    if (t == 0) g_part[blockIdx.x] = sm[0];
}
__global__ void scan2_kernel()
{
    __shared__ int sm[256];
    int t = threadIdx.x;
    int v = (t < NB) ? g_part[t] : 0;
    sm[t] = v;
    __syncthreads();
#pragma unroll
    for (int d = 1; d < 256; d <<= 1) {
        int u = (t >= d) ? sm[t - d] : 0;
        __syncthreads();
        sm[t] += u;
        __syncthreads();
    }
    if (t < NB) g_part[t] = sm[t] - v;
    if (t == 0) g_off[NN] = EE;
}
__global__ void scan3_kernel()
{
    __shared__ int sm[256];
    int t = threadIdx.x;
    int i = blockIdx.x * 256 + t;
    int v = (i < NN) ? g_deg[i] - 1 : 0;
    sm[t] = v;
    __syncthreads();
#pragma unroll
    for (int d = 1; d < 256; d <<= 1) {
        int u = (t >= d) ? sm[t - d] : 0;
        __syncthreads();
        sm[t] += u;
        __syncthreads();
    }
    if (i < NN) {
        int off = g_part[blockIdx.x] + sm[t] - v;
        g_off[i] = off;
        g_cur[i] = off;
    }
}

__global__ void fill_kernel(const int* __restrict__ ei)
{
    int e = blockIdx.x * blockDim.x + threadIdx.x;
    if (e >= EE) return;
    int r = ei[e];
    int c = ei[EE + e];
    int pos = atomicAdd(&g_cur[c], 1);
    g_rows[pos] = r;
    g_nrm[pos]  = g_dinv[r] * g_dinv[c];
}

// ---------------- KAN GEMM via mma.sync — software-pipelined double buffer ----------
// Y[128-tile, 128] = phi(X) @ W^T, bf16 3-term split. 512 thr = 16 warps (4x4),
// warp tile 32x32. K-chunk 64. Two 64KB stages; B via cp.async; 1 sync/chunk.
#define STG   65536
#define DSMEM (2 * STG)

__device__ __forceinline__ void fillB_async(unsigned sb, unsigned tb, int tid,
                                            const __nv_bfloat16* WH,
                                            const __nv_bfloat16* WL,
                                            int Ktot, int k0)
{
#pragma unroll
    for (int j = 0; j < 2; ++j) {
        int idx = tid + 512 * j;
        int o = idx >> 3, u = idx & 7;
        unsigned so = SWZ(o * 128 + u * 16);
        CPASYNC16(sb + tb + 32768u + so, WH + (size_t)o * Ktot + k0 + u * 8);
        CPASYNC16(sb + tb + 49152u + so, WL + (size_t)o * Ktot + k0 + u * 8);
    }
    CPCOMMIT();
}

__device__ __forceinline__ void phi_fill(char* smem, unsigned tb, int row, int d, float x)
{
    float s1, c1;
    __sincosf(x, &s1, &c1);
    float ck = c1, sk = s1;
    unsigned chi[4], clo[4], shi[4], slo[4];
#pragma unroll
    for (int p = 0; p < 4; ++p) {
        float ca = ck, sa = sk;
        float cn = ck * c1 - sk * s1;
        sk = sk * c1 + ck * s1;
        ck = cn;
        float cb = ck, sb2 = sk;
        cn = ck * c1 - sk * s1;
        sk = sk * c1 + ck * s1;
        ck = cn;
        unsigned cau = __float_as_uint(ca), cbu = __float_as_uint(cb);
        unsigned sau = __float_as_uint(sa), sbu = __float_as_uint(sb2);
        PACKHI(chi[p], cau, cbu);
        PACKHI(shi[p], sau, sbu);
        float cah = __uint_as_float(cau & 0xFFFF0000u);
        float cbh = __uint_as_float(cbu & 0xFFFF0000u);
        float sah = __uint_as_float(sau & 0xFFFF0000u);
        float sbh = __uint_as_float(sbu & 0xFFFF0000u);
        PACKLO(clo[p], cb - cbh, ca - cah);
        PACKLO(slo[p], sb2 - sbh, sa - sah);
    }
    unsigned oc = SWZ(row * 128 + d * 32);
    unsigned os = SWZ(row * 128 + d * 32 + 16);
    *(uint4*)(smem + tb + oc)          = make_uint4(chi[0], chi[1], chi[2], chi[3]);
    *(uint4*)(smem + tb + os)          = make_uint4(shi[0], shi[1], shi[2], shi[3]);
    *(uint4*)(smem + tb + 16384u + oc) = make_uint4(clo[0], clo[1], clo[2], clo[3]);
    *(uint4*)(smem + tb + 16384u + os) = make_uint4(slo[0], slo[1], slo[2], slo[3]);
}

template <int INDIM>
__global__ void __launch_bounds__(512) kan_tc(const float* __restrict__ Xext, int sel)
{
    extern __shared__ char smem[];
    const unsigned sb = s2u(smem);

    const int tid = threadIdx.x, wid = tid >> 5, lane = tid & 31;
    const int rowBase = blockIdx.x * 128;
    const int Ktot = INDIM * 16;
    const int NCHK = INDIM / 4;

    const float* X = (sel == 0) ? Xext : g_h;
    float*       Y = (sel == 0) ? g_h  : g_hk;
    const __nv_bfloat16* WH = (sel == 0) ? g_wbh_e : g_wbh_m + (size_t)(sel - 1) * 262144;
    const __nv_bfloat16* WL = (sel == 0) ? g_wbl_e : g_wbl_m + (size_t)(sel - 1) * 262144;

    const int wm = wid & 3;
    const int wn = wid >> 2;

    const int aRow = wm * 32 + (lane & 15);
    const unsigned aColH = ((unsigned)lane >> 4) * 16;
    unsigned aRaw[2];
    aRaw[0] = (unsigned)aRow * 128 + aColH;
    aRaw[1] = (unsigned)(aRow + 16) * 128 + aColH;
    const int bRow = wn * 32 + ((lane >> 4) & 1) * 8 + (lane & 7);
    const unsigned bColH = (((unsigned)lane >> 3) & 1) * 16;
    unsigned bRaw[2];
    bRaw[0] = (unsigned)bRow * 128 + bColH;
    bRaw[1] = (unsigned)(bRow + 16) * 128 + bColH;

    float acc[2][4][4];
#pragma unroll
    for (int i = 0; i < 2; ++i)
#pragma unroll
        for (int j = 0; j < 4; ++j)
#pragma unroll
            for (int q = 0; q < 4; ++q) acc[i][j][q] = 0.f;

    const int prow = tid & 127, pd = tid >> 7;
    const int pr = rowBase + prow;

    // prologue: stage 0
    {
        float x0 = (pr < NN) ? X[(size_t)pr * INDIM + pd] : 0.f;
        fillB_async(sb, 0, tid, WH, WL, Ktot, 0);
        phi_fill(smem, 0, prow, pd, x0);
        CPWAIT0();
    }
    __syncthreads();

    for (int ch = 0; ch < NCHK; ++ch) {
        const unsigned tb  = (unsigned)(ch & 1) * STG;
        const unsigned tbn = tb ^ STG;
        float xn = 0.f;
        if (ch + 1 < NCHK) {
            fillB_async(sb, tbn, tid, WH, WL, Ktot, (ch + 1) * 64);
            if (pr < NN) xn = X[(size_t)pr * INDIM + (ch + 1) * 4 + pd];
        }

        // ---- compute chunk ch from stage tb (overlaps in-flight cp.async) ----
#pragma unroll
        for (int ks = 0; ks < 4; ++ks) {
            unsigned ah[2][4], al[2][4], bh[4][2], bl[4][2];
#pragma unroll
            for (int mt = 0; mt < 2; ++mt) {
                unsigned off = SWZ(aRaw[mt] + ks * 32);
                LDSM4(ah[mt][0], ah[mt][1], ah[mt][2], ah[mt][3], sb + tb + off);
                LDSM4(al[mt][0], al[mt][1], al[mt][2], al[mt][3], sb + tb + 16384u + off);
            }
#pragma unroll
            for (int p = 0; p < 2; ++p) {
                unsigned off = SWZ(bRaw[p] + ks * 32);
                LDSM4(bh[2 * p][0], bh[2 * p][1], bh[2 * p + 1][0], bh[2 * p + 1][1],
                      sb + tb + 32768u + off);
                LDSM4(bl[2 * p][0], bl[2 * p][1], bl[2 * p + 1][0], bl[2 * p + 1][1],
                      sb + tb + 49152u + off);
            }
#pragma unroll
            for (int mt = 0; mt < 2; ++mt)
#pragma unroll
                for (int nt = 0; nt < 4; ++nt) {
                    MMA_BF16(acc[mt][nt], ah[mt], bh[nt]);
                    MMA_BF16(acc[mt][nt], al[mt], bh[nt]);
                    MMA_BF16(acc[mt][nt], ah[mt], bl[nt]);
                }
        }

        if (ch + 1 < NCHK) {
            phi_fill(smem, tbn, prow, pd, xn);
            CPWAIT0();
        }
        __syncthreads();
    }

    // ---- epilogue: fragment -> gmem (float2 per row) ----
    const int gid = lane >> 2, tig = lane & 3;
#pragma unroll
    for (int mt = 0; mt < 2; ++mt)
#pragma unroll
        for (int nt = 0; nt < 4; ++nt) {
            int r0  = rowBase + wm * 32 + mt * 16 + gid;
            int col = wn * 32 + nt * 8 + tig * 2;
            if (r0 < NN)
                *(float2*)(Y + (size_t)r0 * 128 + col) =
                    make_float2(acc[mt][nt][0], acc[mt][nt][1]);
            if (r0 + 8 < NN)
                *(float2*)(Y + (size_t)(r0 + 8) * 128 + col) =
                    make_float2(acc[mt][nt][2], acc[mt][nt][3]);
        }
}

// ---------------- aggregation (CSR gather-sum, one warp per node, MLP=8) -------------
__global__ void agg_kernel()
{
    int w    = (blockIdx.x * blockDim.x + threadIdx.x) >> 5;
    int lane = threadIdx.x & 31;
    if (w >= NN) return;

    float di = g_dinv[w];
    const float4* hk4 = (const float4*)g_hk;
    float4 v = hk4[(size_t)w * 32 + lane];
    float dd = di * di;
    float4 acc = make_float4(dd * v.x, dd * v.y, dd * v.z, dd * v.w);

    int s = g_off[w], e = g_off[w + 1];
    int idx = s;
    for (; idx + 8 <= e; idx += 8) {
        int   rr[8];
        float nn[8];
#pragma unroll
        for (int j = 0; j < 8; ++j) { rr[j] = g_rows[idx + j]; nn[j] = g_nrm[idx + j]; }
        float4 uu[8];
#pragma unroll
        for (int j = 0; j < 8; ++j) uu[j] = hk4[(size_t)rr[j] * 32 + lane];
#pragma unroll
        for (int j = 0; j < 8; ++j) {
            acc.x = fmaf(nn[j], uu[j].x, acc.x);
            acc.y = fmaf(nn[j], uu[j].y, acc.y);
            acc.z = fmaf(nn[j], uu[j].z, acc.z);
            acc.w = fmaf(nn[j], uu[j].w, acc.w);
        }
    }
    for (; idx < e; ++idx) {
        int   r  = g_rows[idx];
        float nm = g_nrm[idx];
        float4 u = hk4[(size_t)r * 32 + lane];
        acc.x = fmaf(nm, u.x, acc.x);
        acc.y = fmaf(nm, u.y, acc.y);
        acc.z = fmaf(nm, u.z, acc.z);
        acc.w = fmaf(nm, u.w, acc.w);
    }
    ((float4*)g_h)[(size_t)w * 32 + lane] = acc;
}

// ---------------- mean pool (batch sorted) ----------------
__global__ void pool_kernel(const int* __restrict__ batch)
{
    int g = blockIdx.x;
    int f = threadIdx.x;

    int lo = 0, hi = NN;
    while (lo < hi) { int m = (lo + hi) >> 1; if (batch[m] < g) lo = m + 1; else hi = m; }
    int st = lo;
    lo = 0; hi = NN;
    while (lo < hi) { int m = (lo + hi) >> 1; if (batch[m] < g + 1) lo = m + 1; else hi = m; }
    int en = lo;

    float acc = 0.f;
    for (int n = st; n < en; ++n) acc += g_h[(size_t)n * 128 + f];
    float cnt = (float)(en - st);
    g_pool[g * 128 + f] = acc / fmaxf(cnt, 1.0f);
}

// ---------------- readout (fp32) ----------------
__global__ void read_kernel(float* __restrict__ out)
{
    __shared__ float phi[2048];
    __shared__ float part[32 * 8];
    int g   = blockIdx.x;
    int tid = threadIdx.x;

    if (tid < 128) {
        float x = g_pool[g * 128 + tid];
        float s1, c1;
        sincosf(x, &s1, &c1);
        float ck = c1, sk = s1;
#pragma unroll
        for (int hh = 0; hh < 8; ++hh) {
            phi[tid * 16 + hh]     = ck;
            phi[tid * 16 + 8 + hh] = sk;
            float cn = ck * c1 - sk * s1;
            sk = sk * c1 + ck * s1;
            ck = cn;
        }
    }
    __syncthreads();

    int o = tid >> 3, sg = tid & 7;
    float acc = 0.f;
    int k0 = sg * 256;
    for (int k = k0; k < k0 + 256; ++k)
        acc = fmaf(phi[k], g_wtr[k * 32 + o], acc);
    part[o * 8 + sg] = acc;
    __syncthreads();

    if (tid < 32) {
        float s = 0.f;
#pragma unroll
        for (int j = 0; j < 8; ++j) s += part[tid * 8 + j];
        out[g * 32 + tid] = s;
    }
}

// ---------------- launch ----------------
extern "C" void kernel_launch(void* const* d_in, const int* in_sizes, int n_in,
                              void* d_out, int out_size)
{
    const float* features = (const float*)d_in[0];
    const int*   ei       = (const int*)  d_in[1];
    const int*   batch    = (const int*)  d_in[2];
    const float* W_embed  = (const float*)d_in[3];
    const float* W_mp     = (const float*)d_in[4];
    const float* W_read   = (const float*)d_in[5];
    float* out = (float*)d_out;

    cudaFuncSetAttribute(kan_tc<64>,  cudaFuncAttributeMaxDynamicSharedMemorySize, DSMEM);
    cudaFuncSetAttribute(kan_tc<128>, cudaFuncAttributeMaxDynamicSharedMemorySize, DSMEM);

    const int GK = (NN + 127) / 128;   // 391 tiles

    // ordered so the 4th launch (= what ncu captures) is the dominant kan_tc<128>
    prep_kernel<<<(131072 + 3 * 262144 + 65536 + NN + 255) / 256, 256>>>(W_embed, W_mp, W_read);
    kan_tc<64><<<GK, 512, DSMEM>>>(features, 0);           // embed (needs prep only)
    deg_count_kernel<<<(EE + 255) / 256, 256>>>(ei);
    kan_tc<128><<<GK, 512, DSMEM>>>(features, 1);          // mp layer 0 GEMM  [profiled]
    dinv_kernel<<<(NN + 255) / 256, 256>>>();
    scan1_kernel<<<NB, 256>>>();
    scan2_kernel<<<1, 256>>>();
    scan3_kernel<<<NB, 256>>>();
    fill_kernel<<<(EE + 255) / 256, 256>>>(ei);
    agg_kernel<<<(NN * 32 + 255) / 256, 256>>>();          // layer 0 aggregate

    for (int l = 1; l < NL; ++l) {
        kan_tc<128><<<GK, 512, DSMEM>>>(features, l + 1);
        agg_kernel<<<(NN * 32 + 255) / 256, 256>>>();
    }

    pool_kernel<<<NG, 128>>>(batch);
    read_kernel<<<NG, 256>>>(out);
}

// round 17
// speedup vs baseline: 3.0220x; 1.2303x over previous
#include <cuda_runtime.h>
#include <cuda_bf16.h>
#include <cuda_fp16.h>
#include <cstdint>
#include <stdint.h>
#include <math.h>

// Problem constants
#define NN   50000
#define EE   1600000
#define INF  64
#define HIDF 128
#define NG   64
#define NL   3
#define NB   196      // scan blocks: ceil(NN/256)

// ---------------- scratch (__device__ globals; no runtime allocation) ----------------
__device__ float g_h [NN * HIDF];
__device__ float g_hk[NN * HIDF];
__device__ int   g_deg [NN];
__device__ float g_dinv[NN];
__device__ int   g_off [NN + 1];
__device__ int   g_cur [NN];
__device__ int   g_part[256];
__device__ int   g_rows[EE];
__device__ float g_nrm [EE];
__device__ __half g_wh_e[128 * 1024];       // embed W hi fp16, [o][k]
__device__ __half g_wl_e[128 * 1024];       // embed W lo fp16
__device__ __half g_wh_m[3 * 128 * 2048];   // mp W hi fp16, [l][o][k]
__device__ __half g_wl_m[3 * 128 * 2048];   // mp W lo fp16
__device__ float g_wtr [2048 * 32];         // readout W fp32, [k][o]
__device__ float g_pool[NG * HIDF];

// ---------------- PTX helpers (base-target legal) ----------------
__device__ __forceinline__ unsigned s2u(const void* p)
{
    unsigned a;
    asm("{ .reg .u64 t; cvta.to.shared.u64 t, %1; cvt.u32.u64 %0, t; }" : "=r"(a) : "l"(p));
    return a;
}

#define LDSM4(r0, r1, r2, r3, addr) \
    asm volatile("ldmatrix.sync.aligned.m8n8.x4.shared.b16 {%0,%1,%2,%3}, [%4];" \
                 : "=r"(r0), "=r"(r1), "=r"(r2), "=r"(r3) : "r"(addr))

#define MMA_F16(c, a, b) \
    asm volatile("mma.sync.aligned.m16n8k16.row.col.f32.f16.f16.f32 " \
                 "{%0,%1,%2,%3}, {%4,%5,%6,%7}, {%8,%9}, {%0,%1,%2,%3};" \
                 : "+f"((c)[0]), "+f"((c)[1]), "+f"((c)[2]), "+f"((c)[3]) \
                 : "r"((a)[0]), "r"((a)[1]), "r"((a)[2]), "r"((a)[3]), \
                   "r"((b)[0]), "r"((b)[1]))

// pack two fp32 to f16x2: first PTX src -> high half
#define PACKF16(d, fb, fa) \
    asm("cvt.rn.f16x2.f32 %0, %1, %2;" : "=r"(d) : "f"(fb), "f"(fa))

#define CPASYNC16(sa, ga) \
    asm volatile("cp.async.cg.shared.global [%0], [%1], 16;" :: "r"(sa), "l"(ga))
#define CPCOMMIT() asm volatile("cp.async.commit_group;" ::: "memory")
#define CPWAIT0()  asm volatile("cp.async.wait_group 0;" ::: "memory")

#define SWZ(x) ((unsigned)(x) ^ (((unsigned)(x) >> 3) & 0x70u))

// ---------------- prep: weight split to fp16 hi/lo + read transpose + deg init ------
__global__ void prep_kernel(const float* __restrict__ We,
                            const float* __restrict__ Wm,
                            const float* __restrict__ Wr)
{
    int idx = blockIdx.x * blockDim.x + threadIdx.x;
    if (idx < 131072) {                       // embed: OUT=128, IN=64, K=1024
        int o = idx >> 10, k = idx & 1023;
        int i = k >> 4, t = (k >> 3) & 1, h = k & 7;
        float v = We[(((t * 128 + o) * 64 + i) << 3) + h];
        __half hi = __float2half_rn(v);
        g_wh_e[idx] = hi;
        g_wl_e[idx] = __float2half_rn(v - __half2float(hi));
        return;
    }
    idx -= 131072;
    if (idx < 3 * 262144) {                   // mp: OUT=128, IN=128, K=2048
        int l = idx / 262144, r = idx % 262144;
        int o = r >> 11, k = r & 2047;
        int i = k >> 4, t = (k >> 3) & 1, h = k & 7;
        float v = Wm[(size_t)l * 262144 + (((t * 128 + o) * 128 + i) << 3) + h];
        __half hi = __float2half_rn(v);
        g_wh_m[(size_t)l * 262144 + r] = hi;
        g_wl_m[(size_t)l * 262144 + r] = __float2half_rn(v - __half2float(hi));
        return;
    }
    idx -= 3 * 262144;
    if (idx < 65536) {                        // readout fp32 transpose: [k][o], OUT=32, IN=128
        int o = idx & 31, k = idx >> 5;
        int i = k >> 4, t = (k >> 3) & 1, h = k & 7;
        g_wtr[idx] = Wr[(((t * 32 + o) * 128 + i) << 3) + h];
        return;
    }
    idx -= 65536;
    if (idx < NN) g_deg[idx] = 1;             // self loop
}

// ---------------- degree / dinv ----------------
__global__ void deg_count_kernel(const int* __restrict__ ei)
{
    int e = blockIdx.x * blockDim.x + threadIdx.x;
    if (e < EE) atomicAdd(&g_deg[ei[EE + e]], 1);
}
__global__ void dinv_kernel()
{
    int i = blockIdx.x * blockDim.x + threadIdx.x;
    if (i < NN) g_dinv[i] = rsqrtf((float)g_deg[i]);
}

// ---------------- parallel CSR scan: 3 small kernels ----------------
__global__ void scan1_kernel()
{
    __shared__ int sm[256];
    int t = threadIdx.x;
    int i = blockIdx.x * 256 + t;
    sm[t] = (i < NN) ? g_deg[i] - 1 : 0;
    __syncthreads();
#pragma unroll
    for (int d = 128; d > 0; d >>= 1) {
        if (t < d) sm[t] += sm[t + d];
        __syncthreads();
    }
    if (t == 0) g_part[blockIdx.x] = sm[0];
}
__global__ void scan2_kernel()
{
    __shared__ int sm[256];
    int t = threadIdx.x;
    int v = (t < NB) ? g_part[t] : 0;
    sm[t] = v;
    __syncthreads();
#pragma unroll
    for (int d = 1; d < 256; d <<= 1) {
        int u = (t >= d) ? sm[t - d] : 0;
        __syncthreads();
        sm[t] += u;
        __syncthreads();
    }
    if (t < NB) g_part[t] = sm[t] - v;
    if (t == 0) g_off[NN] = EE;
}
__global__ void scan3_kernel()
{
    __shared__ int sm[256];
    int t = threadIdx.x;
    int i = blockIdx.x * 256 + t;
    int v = (i < NN) ? g_deg[i] - 1 : 0;
    sm[t] = v;
    __syncthreads();
#pragma unroll
    for (int d = 1; d < 256; d <<= 1) {
        int u = (t >= d) ? sm[t - d] : 0;
        __syncthreads();
        sm[t] += u;
        __syncthreads();
    }
    if (i < NN) {
        int off = g_part[blockIdx.x] + sm[t] - v;
        g_off[i] = off;
        g_cur[i] = off;
    }
}

__global__ void fill_kernel(const int* __restrict__ ei)
{
    int e = blockIdx.x * blockDim.x + threadIdx.x;
    if (e >= EE) return;
    int r = ei[e];
    int c = ei[EE + e];
    int pos = atomicAdd(&g_cur[c], 1);
    g_rows[pos] = r;
    g_nrm[pos]  = g_dinv[r] * g_dinv[c];
}

// ---------------- KAN GEMM via mma.sync — fp16 2-term, pipelined -------------------
// Y = phi(X) @ W^T: terms a*bh + a*bl (a = fp16(phi), b = bh + bl fp16 split).
// 512 thr = 16 warps (4x4), warp tile 32x32, K-chunk 64.
// Stage (48KB): A fp16 @0 (16KB), BH @16384, BL @32768. Double-buffered stages,
// fragment-level double buffering inside the chunk.
#define STG   49152
#define DSMEM (2 * STG)

__device__ __forceinline__ void fillB_async(unsigned sb, unsigned tb, int tid,
                                            const __half* WH, const __half* WL,
                                            int Ktot, int k0)
{
#pragma unroll
    for (int j = 0; j < 2; ++j) {
        int idx = tid + 512 * j;
        int o = idx >> 3, u = idx & 7;
        unsigned so = SWZ(o * 128 + u * 16);
        CPASYNC16(sb + tb + 16384u + so, WH + (size_t)o * Ktot + k0 + u * 8);
        CPASYNC16(sb + tb + 32768u + so, WL + (size_t)o * Ktot + k0 + u * 8);
    }
    CPCOMMIT();
}

__device__ __forceinline__ void phi_fill(char* smem, unsigned tb, int row, int d, float x)
{
    float s1, c1;
    __sincosf(x, &s1, &c1);
    float ck = c1, sk = s1;
    unsigned ch2[4], sh2[4];
#pragma unroll
    for (int p = 0; p < 4; ++p) {
        float ca = ck, sa = sk;
        float cn = ck * c1 - sk * s1;
        sk = sk * c1 + ck * s1;
        ck = cn;
        float cb = ck, sb2 = sk;
        cn = ck * c1 - sk * s1;
        sk = sk * c1 + ck * s1;
        ck = cn;
        PACKF16(ch2[p], cb, ca);
        PACKF16(sh2[p], sb2, sa);
    }
    unsigned oc = SWZ(row * 128 + d * 32);
    unsigned os = SWZ(row * 128 + d * 32 + 16);
    *(uint4*)(smem + tb + oc) = make_uint4(ch2[0], ch2[1], ch2[2], ch2[3]);
    *(uint4*)(smem + tb + os) = make_uint4(sh2[0], sh2[1], sh2[2], sh2[3]);
}

template <int INDIM>
__global__ void __launch_bounds__(512) kan_tc(const float* __restrict__ Xext, int sel)
{
    extern __shared__ char smem[];
    const unsigned sb = s2u(smem);

    const int tid = threadIdx.x, wid = tid >> 5, lane = tid & 31;
    const int rowBase = blockIdx.x * 128;
    const int Ktot = INDIM * 16;
    const int NCHK = INDIM / 4;

    const float* X = (sel == 0) ? Xext : g_h;
    float*       Y = (sel == 0) ? g_h  : g_hk;
    const __half* WH = (sel == 0) ? g_wh_e : g_wh_m + (size_t)(sel - 1) * 262144;
    const __half* WL = (sel == 0) ? g_wl_e : g_wl_m + (size_t)(sel - 1) * 262144;

    const int wm = wid & 3;
    const int wn = wid >> 2;

    const int aRow = wm * 32 + (lane & 15);
    const unsigned aColH = ((unsigned)lane >> 4) * 16;
    unsigned aRaw[2];
    aRaw[0] = (unsigned)aRow * 128 + aColH;
    aRaw[1] = (unsigned)(aRow + 16) * 128 + aColH;
    const int bRow = wn * 32 + ((lane >> 4) & 1) * 8 + (lane & 7);
    const unsigned bColH = (((unsigned)lane >> 3) & 1) * 16;
    unsigned bRaw[2];
    bRaw[0] = (unsigned)bRow * 128 + bColH;
    bRaw[1] = (unsigned)(bRow + 16) * 128 + bColH;

    float acc[2][4][4];
#pragma unroll
    for (int i = 0; i < 2; ++i)
#pragma unroll
        for (int j = 0; j < 4; ++j)
#pragma unroll
            for (int q = 0; q < 4; ++q) acc[i][j][q] = 0.f;

    const int prow = tid & 127, pd = tid >> 7;
    const int pr = rowBase + prow;

    // prologue: stage 0
    {
        float x0 = (pr < NN) ? X[(size_t)pr * INDIM + pd] : 0.f;
        fillB_async(sb, 0, tid, WH, WL, Ktot, 0);
        phi_fill(smem, 0, prow, pd, x0);
        CPWAIT0();
    }
    __syncthreads();

    for (int ch = 0; ch < NCHK; ++ch) {
        const unsigned tb  = (unsigned)(ch & 1) * STG;
        const unsigned tbn = tb ^ STG;
        float xn = 0.f;
        if (ch + 1 < NCHK) {
            fillB_async(sb, tbn, tid, WH, WL, Ktot, (ch + 1) * 64);
            if (pr < NN) xn = X[(size_t)pr * INDIM + (ch + 1) * 4 + pd];
        }

        // ---- compute chunk ch, fragment double-buffered across k-steps ----
        unsigned a0[2][4], bh0[4][2], bl0[4][2];
        {
            unsigned offA0 = SWZ(aRaw[0]), offA1 = SWZ(aRaw[1]);
            LDSM4(a0[0][0], a0[0][1], a0[0][2], a0[0][3], sb + tb + offA0);
            LDSM4(a0[1][0], a0[1][1], a0[1][2], a0[1][3], sb + tb + offA1);
            unsigned offB0 = SWZ(bRaw[0]), offB1 = SWZ(bRaw[1]);
            LDSM4(bh0[0][0], bh0[0][1], bh0[1][0], bh0[1][1], sb + tb + 16384u + offB0);
            LDSM4(bh0[2][0], bh0[2][1], bh0[3][0], bh0[3][1], sb + tb + 16384u + offB1);
            LDSM4(bl0[0][0], bl0[0][1], bl0[1][0], bl0[1][1], sb + tb + 32768u + offB0);
            LDSM4(bl0[2][0], bl0[2][1], bl0[3][0], bl0[3][1], sb + tb + 32768u + offB1);
        }
#pragma unroll
        for (int ks = 0; ks < 4; ++ks) {
            unsigned a1[2][4], bh1[4][2], bl1[4][2];
            if (ks < 3) {
                unsigned offA0 = SWZ(aRaw[0] + (ks + 1) * 32);
                unsigned offA1 = SWZ(aRaw[1] + (ks + 1) * 32);
                LDSM4(a1[0][0], a1[0][1], a1[0][2], a1[0][3], sb + tb + offA0);
                LDSM4(a1[1][0], a1[1][1], a1[1][2], a1[1][3], sb + tb + offA1);
                unsigned offB0 = SWZ(bRaw[0] + (ks + 1) * 32);
                unsigned offB1 = SWZ(bRaw[1] + (ks + 1) * 32);
                LDSM4(bh1[0][0], bh1[0][1], bh1[1][0], bh1[1][1], sb + tb + 16384u + offB0);
                LDSM4(bh1[2][0], bh1[2][1], bh1[3][0], bh1[3][1], sb + tb + 16384u + offB1);
                LDSM4(bl1[0][0], bl1[0][1], bl1[1][0], bl1[1][1], sb + tb + 32768u + offB0);
                LDSM4(bl1[2][0], bl1[2][1], bl1[3][0], bl1[3][1], sb + tb + 32768u + offB1);
            }
#pragma unroll
            for (int mt = 0; mt < 2; ++mt)
#pragma unroll
                for (int nt = 0; nt < 4; ++nt) {
                    MMA_F16(acc[mt][nt], a0[mt], bh0[nt]);
                    MMA_F16(acc[mt][nt], a0[mt], bl0[nt]);
                }
            if (ks < 3) {
#pragma unroll
                for (int mt = 0; mt < 2; ++mt)
#pragma unroll
                    for (int q = 0; q < 4; ++q) a0[mt][q] = a1[mt][q];
#pragma unroll
                for (int nt = 0; nt < 4; ++nt)
#pragma unroll
                    for (int q = 0; q < 2; ++q) {
                        bh0[nt][q] = bh1[nt][q];
                        bl0[nt][q] = bl1[nt][q];
                    }
            }
        }

        if (ch + 1 < NCHK) {
            phi_fill(smem, tbn, prow, pd, xn);
            CPWAIT0();
        }
        __syncthreads();
    }

    // ---- epilogue: fragment -> gmem (float2 per row) ----
    const int gid = lane >> 2, tig = lane & 3;
#pragma unroll
    for (int mt = 0; mt < 2; ++mt)
#pragma unroll
        for (int nt = 0; nt < 4; ++nt) {
            int r0  = rowBase + wm * 32 + mt * 16 + gid;
            int col = wn * 32 + nt * 8 + tig * 2;
            if (r0 < NN)
                *(float2*)(Y + (size_t)r0 * 128 + col) =
                    make_float2(acc[mt][nt][0], acc[mt][nt][1]);
            if (r0 + 8 < NN)
                *(float2*)(Y + (size_t)(r0 + 8) * 128 + col) =
                    make_float2(acc[mt][nt][2], acc[mt][nt][3]);
        }
}

// ---------------- aggregation (CSR gather-sum, one warp per node, MLP=8) -------------
__global__ void agg_kernel()
{
    int w    = (blockIdx.x * blockDim.x + threadIdx.x) >> 5;
    int lane = threadIdx.x & 31;
    if (w >= NN) return;

    float di = g_dinv[w];
    const float4* hk4 = (const float4*)g_hk;
    float4 v = hk4[(size_t)w * 32 + lane];
    float dd = di * di;
    float4 acc = make_float4(dd * v.x, dd * v.y, dd * v.z, dd * v.w);

    int s = g_off[w], e = g_off[w + 1];
    int idx = s;
    for (; idx + 8 <= e; idx += 8) {
        int   rr[8];
        float nn[8];
#pragma unroll
        for (int j = 0; j < 8; ++j) { rr[j] = g_rows[idx + j]; nn[j] = g_nrm[idx + j]; }
        float4 uu[8];
#pragma unroll
        for (int j = 0; j < 8; ++j) uu[j] = hk4[(size_t)rr[j] * 32 + lane];
#pragma unroll
        for (int j = 0; j < 8; ++j) {
            acc.x = fmaf(nn[j], uu[j].x, acc.x);
            acc.y = fmaf(nn[j], uu[j].y, acc.y);
            acc.z = fmaf(nn[j], uu[j].z, acc.z);
            acc.w = fmaf(nn[j], uu[j].w, acc.w);
        }
    }
    for (; idx < e; ++idx) {
        int   r  = g_rows[idx];
        float nm = g_nrm[idx];
        float4 u = hk4[(size_t)r * 32 + lane];
        acc.x = fmaf(nm, u.x, acc.x);
        acc.y = fmaf(nm, u.y, acc.y);
        acc.z = fmaf(nm, u.z, acc.z);
        acc.w = fmaf(nm, u.w, acc.w);
    }
    ((float4*)g_h)[(size_t)w * 32 + lane] = acc;
}

// ---------------- mean pool (batch sorted) ----------------
__global__ void pool_kernel(const int* __restrict__ batch)
{
    int g = blockIdx.x;
    int f = threadIdx.x;

    int lo = 0, hi = NN;
    while (lo < hi) { int m = (lo + hi) >> 1; if (batch[m] < g) lo = m + 1; else hi = m; }
    int st = lo;
    lo = 0; hi = NN;
    while (lo < hi) { int m = (lo + hi) >> 1; if (batch[m] < g + 1) lo = m + 1; else hi = m; }
    int en = lo;

    float acc = 0.f;
    for (int n = st; n < en; ++n) acc += g_h[(size_t)n * 128 + f];
    float cnt = (float)(en - st);
    g_pool[g * 128 + f] = acc / fmaxf(cnt, 1.0f);
}

// ---------------- readout (fp32) ----------------
__global__ void read_kernel(float* __restrict__ out)
{
    __shared__ float phi[2048];
    __shared__ float part[32 * 8];
    int g   = blockIdx.x;
    int tid = threadIdx.x;

    if (tid < 128) {
        float x = g_pool[g * 128 + tid];
        float s1, c1;
        sincosf(x, &s1, &c1);
        float ck = c1, sk = s1;
#pragma unroll
        for (int hh = 0; hh < 8; ++hh) {
            phi[tid * 16 + hh]     = ck;
            phi[tid * 16 + 8 + hh] = sk;
            float cn = ck * c1 - sk * s1;
            sk = sk * c1 + ck * s1;
            ck = cn;
        }
    }
    __syncthreads();

    int o = tid >> 3, sg = tid & 7;
    float acc = 0.f;
    int k0 = sg * 256;
    for (int k = k0; k < k0 + 256; ++k)
        acc = fmaf(phi[k], g_wtr[k * 32 + o], acc);
    part[o * 8 + sg] = acc;
    __syncthreads();

    if (tid < 32) {
        float s = 0.f;
#pragma unroll
        for (int j = 0; j < 8; ++j) s += part[tid * 8 + j];
        out[g * 32 + tid] = s;
    }
}

// ---------------- launch ----------------
extern "C" void kernel_launch(void* const* d_in, const int* in_sizes, int n_in,
                              void* d_out, int out_size)
{
    const float* features = (const float*)d_in[0];
    const int*   ei       = (const int*)  d_in[1];
    const int*   batch    = (const int*)  d_in[2];
    const float* W_embed  = (const float*)d_in[3];
    const float* W_mp     = (const float*)d_in[4];
    const float* W_read   = (const float*)d_in[5];
    float* out = (float*)d_out;

    cudaFuncSetAttribute(kan_tc<64>,  cudaFuncAttributeMaxDynamicSharedMemorySize, DSMEM);
    cudaFuncSetAttribute(kan_tc<128>, cudaFuncAttributeMaxDynamicSharedMemorySize, DSMEM);

    const int GK = (NN + 127) / 128;   // 391 tiles

    // ordered so the 4th launch (= what ncu captures) is the dominant kan_tc<128>
    prep_kernel<<<(131072 + 3 * 262144 + 65536 + NN + 255) / 256, 256>>>(W_embed, W_mp, W_read);
    kan_tc<64><<<GK, 512, DSMEM>>>(features, 0);           // embed (needs prep only)
    deg_count_kernel<<<(EE + 255) / 256, 256>>>(ei);
    kan_tc<128><<<GK, 512, DSMEM>>>(features, 1);          // mp layer 0 GEMM  [profiled]
    dinv_kernel<<<(NN + 255) / 256, 256>>>();
    scan1_kernel<<<NB, 256>>>();
    scan2_kernel<<<1, 256>>>();
    scan3_kernel<<<NB, 256>>>();
    fill_kernel<<<(EE + 255) / 256, 256>>>(ei);
    agg_kernel<<<(NN * 32 + 255) / 256, 256>>>();          // layer 0 aggregate

    for (int l = 1; l < NL; ++l) {
        kan_tc<128><<<GK, 512, DSMEM>>>(features, l + 1);
        agg_kernel<<<(NN * 32 + 255) / 256, 256>>>();
    }

    pool_kernel<<<NG, 128>>>(batch);
    read_kernel<<<NG, 256>>>(out);
}